// round 1
// baseline (speedup 1.0000x reference)
#include <cuda_runtime.h>
#include <cuda_bf16.h>
#include <cstddef>

// Problem constants
#define N_NEWS 10000
#define N_INT  50000
#define N_ALL  60000
#define F_IN   768
#define H      256
#define OUTD   8

// ---------------- device scratch (no allocations allowed) ----------------
__device__ float g_XA[N_ALL * H];
__device__ float g_XB[N_ALL * H];
__device__ float g_O [N_ALL * H];
__device__ float g_A0[N_NEWS * H];
__device__ float g_A1[N_INT  * H];
__device__ float g_A2[N_NEWS * H];

__device__ int   g_deg0[N_NEWS], g_deg1[N_INT], g_deg2[N_NEWS];
__device__ float g_inv0[N_NEWS], g_inv1[N_INT], g_inv2[N_NEWS];
__device__ int   g_off0[N_NEWS + 1], g_off1[N_INT + 1], g_off2[N_NEWS + 1];
__device__ int   g_cur0[N_NEWS], g_cur1[N_INT], g_cur2[N_NEWS];
__device__ int   g_srt0[500000], g_srt1[400000], g_srt2[400000];

// ---------------- degree / inv-degree ----------------
__global__ void deg_kernel(const int* __restrict__ dst, int n, int* __restrict__ deg) {
    int i = blockIdx.x * blockDim.x + threadIdx.x;
    if (i < n) atomicAdd(&deg[dst[i]], 1);
}

__global__ void invdeg_kernel(const int* __restrict__ deg, float* __restrict__ inv, int n) {
    int i = blockIdx.x * blockDim.x + threadIdx.x;
    if (i < n) {
        int d = deg[i];
        inv[i] = (d > 0) ? (1.0f / (float)d) : 0.0f;
    }
}

// ---------------- single-block exclusive scan (n up to ~50k) ----------------
__global__ void scan_kernel(const int* __restrict__ deg, int* __restrict__ off, int n) {
    __shared__ int sh[1024];
    int carry = 0;
    for (int base = 0; base < n; base += 1024) {
        int i = base + (int)threadIdx.x;
        int v = (i < n) ? deg[i] : 0;
        sh[threadIdx.x] = v;
        __syncthreads();
        #pragma unroll
        for (int s = 1; s < 1024; s <<= 1) {
            int t = (threadIdx.x >= (unsigned)s) ? sh[threadIdx.x - s] : 0;
            __syncthreads();
            sh[threadIdx.x] += t;
            __syncthreads();
        }
        int incl = sh[threadIdx.x];
        int total = sh[1023];
        if (i < n) off[i] = carry + incl - v;
        carry += total;
        __syncthreads();
    }
    if (threadIdx.x == 0) off[n] = carry;
}

// ---------------- CSR fill (src stored as GLOBAL node index) ----------------
__global__ void fill_kernel(const int* __restrict__ src, const int* __restrict__ dst,
                            int n, int srcOffset,
                            int* __restrict__ cur, int* __restrict__ srt) {
    int i = blockIdx.x * blockDim.x + threadIdx.x;
    if (i < n) {
        int p = atomicAdd(&cur[dst[i]], 1);
        srt[p] = src[i] + srcOffset;
    }
}

// ---------------- warp-per-node mean aggregation (gather, no atomics) ------
__global__ void aggregate_kernel(const float* __restrict__ X,
                                 const int* __restrict__ off,
                                 const int* __restrict__ srt,
                                 const float* __restrict__ invdeg,
                                 float* __restrict__ out, int count) {
    int gw   = (int)((blockIdx.x * blockDim.x + threadIdx.x) >> 5);
    int lane = threadIdx.x & 31;
    if (gw >= count) return;
    int e0 = off[gw], e1 = off[gw + 1];
    float4 s0 = make_float4(0.f, 0.f, 0.f, 0.f);
    float4 s1 = make_float4(0.f, 0.f, 0.f, 0.f);
    for (int e = e0; e < e1; e++) {
        int src = srt[e];
        const float4* row = (const float4*)(X + (size_t)src * H);
        float4 v0 = __ldg(&row[lane]);
        float4 v1 = __ldg(&row[lane + 32]);
        s0.x += v0.x; s0.y += v0.y; s0.z += v0.z; s0.w += v0.w;
        s1.x += v1.x; s1.y += v1.y; s1.z += v1.z; s1.w += v1.w;
    }
    float d = invdeg[gw];
    s0.x *= d; s0.y *= d; s0.z *= d; s0.w *= d;
    s1.x *= d; s1.y *= d; s1.z *= d; s1.w *= d;
    float4* o = (float4*)(out + (size_t)gw * H);
    o[lane]      = s0;
    o[lane + 32] = s1;
}

// ---------------- tiled SGEMM: C = A(MxK) * B(Kx256) [+Cin|+bias] [relu] ---
// N fixed at 256, ldb = ldcin = ldcout = 256.
template <bool RELU>
__global__ __launch_bounds__(256) void sgemm_kernel(
    const float* __restrict__ A, int lda,
    const float* __restrict__ B,
    const float* __restrict__ Cin,
    const float* __restrict__ bias,
    float* __restrict__ Cout,
    int M, int K) {
    constexpr int BM = 128, BN = 128, BK = 8;
    __shared__ float As[BK][BM];
    __shared__ float Bs[BK][BN];

    const int tid  = threadIdx.x;
    const int row0 = blockIdx.y * BM;
    const int col0 = blockIdx.x * BN;

    const int aRow = tid >> 1;
    const int aCol = (tid & 1) << 2;
    const int bRow = tid >> 5;
    const int bCol = (tid & 31) << 2;

    const int ty = (tid >> 4) << 3;  // 0..120
    const int tx = (tid & 15) << 3;  // 0..120

    float acc[8][8];
    #pragma unroll
    for (int i = 0; i < 8; i++)
        #pragma unroll
        for (int j = 0; j < 8; j++) acc[i][j] = 0.f;

    const bool  aValid = (row0 + aRow) < M;
    const float* Aptr  = A + (size_t)(row0 + aRow) * lda + aCol;
    const float* Bptr  = B + (size_t)bRow * H + col0 + bCol;

    for (int k0 = 0; k0 < K; k0 += BK) {
        float4 av = aValid ? *(const float4*)(Aptr + k0)
                           : make_float4(0.f, 0.f, 0.f, 0.f);
        float4 bv = *(const float4*)(Bptr + (size_t)k0 * H);
        As[aCol + 0][aRow] = av.x;
        As[aCol + 1][aRow] = av.y;
        As[aCol + 2][aRow] = av.z;
        As[aCol + 3][aRow] = av.w;
        *(float4*)&Bs[bRow][bCol] = bv;
        __syncthreads();

        #pragma unroll
        for (int k = 0; k < BK; k++) {
            float a[8], b[8];
            #pragma unroll
            for (int i = 0; i < 8; i++) a[i] = As[k][ty + i];
            #pragma unroll
            for (int j = 0; j < 8; j++) b[j] = Bs[k][tx + j];
            #pragma unroll
            for (int i = 0; i < 8; i++)
                #pragma unroll
                for (int j = 0; j < 8; j++) acc[i][j] += a[i] * b[j];
        }
        __syncthreads();
    }

    #pragma unroll
    for (int i = 0; i < 8; i++) {
        int r = row0 + ty + i;
        if (r < M) {
            #pragma unroll
            for (int j = 0; j < 8; j += 4) {
                int c = col0 + tx + j;
                float4 v = make_float4(acc[i][j], acc[i][j + 1], acc[i][j + 2], acc[i][j + 3]);
                if (Cin) {
                    float4 ci = *(const float4*)(Cin + (size_t)r * H + c);
                    v.x += ci.x; v.y += ci.y; v.z += ci.z; v.w += ci.w;
                }
                if (bias) {
                    float4 bb = *(const float4*)(bias + c);
                    v.x += bb.x; v.y += bb.y; v.z += bb.z; v.w += bb.w;
                }
                if (RELU) {
                    v.x = fmaxf(v.x, 0.f); v.y = fmaxf(v.y, 0.f);
                    v.z = fmaxf(v.z, 0.f); v.w = fmaxf(v.w, 0.f);
                }
                *(float4*)(Cout + (size_t)r * H + c) = v;
            }
        }
    }
}

// ---------------- final projection: out = X[:10000] @ W(256x8) + b --------
__global__ void out_proj_kernel(const float* __restrict__ X,
                                const float* __restrict__ W,
                                const float* __restrict__ b,
                                float* __restrict__ out) {
    int i = blockIdx.x * 32 + (threadIdx.x >> 3);
    int o = threadIdx.x & 7;
    if (i >= N_NEWS) return;
    float s = b[o];
    const float* x = X + (size_t)i * H;
    #pragma unroll 8
    for (int j = 0; j < H; j++) s += x[j] * __ldg(&W[j * OUTD + o]);
    out[i * OUTD + o] = s;
}

// ---------------- launch ----------------
extern "C" void kernel_launch(void* const* d_in, const int* in_sizes, int n_in,
                              void* d_out, int out_size) {
    const float* x_news = (const float*)d_in[0];
    const float* x_int  = (const float*)d_in[1];
    const float* Wn     = (const float*)d_in[2];
    const float* bn     = (const float*)d_in[3];
    const float* Wi     = (const float*)d_in[4];
    const float* bi     = (const float*)d_in[5];
    const float* W_rel  = (const float*)d_in[6];
    const float* W_root = (const float*)d_in[7];
    const float* conv_b = (const float*)d_in[8];
    const float* out_W  = (const float*)d_in[9];
    const float* out_b  = (const float*)d_in[10];
    const int* e0s = (const int*)d_in[11];
    const int* e0d = (const int*)d_in[12];
    const int* e1s = (const int*)d_in[13];
    const int* e1d = (const int*)d_in[14];
    const int* e2s = (const int*)d_in[15];
    const int* e2d = (const int*)d_in[16];
    const int E0 = in_sizes[11], E1 = in_sizes[13], E2 = in_sizes[15];
    float* out = (float*)d_out;

    float *XA, *XB, *O, *A0, *A1, *A2, *inv0, *inv1, *inv2;
    int *deg0, *deg1, *deg2, *off0, *off1, *off2, *cur0, *cur1, *cur2, *s0, *s1, *s2;
    cudaGetSymbolAddress((void**)&XA, g_XA);
    cudaGetSymbolAddress((void**)&XB, g_XB);
    cudaGetSymbolAddress((void**)&O,  g_O);
    cudaGetSymbolAddress((void**)&A0, g_A0);
    cudaGetSymbolAddress((void**)&A1, g_A1);
    cudaGetSymbolAddress((void**)&A2, g_A2);
    cudaGetSymbolAddress((void**)&deg0, g_deg0);
    cudaGetSymbolAddress((void**)&deg1, g_deg1);
    cudaGetSymbolAddress((void**)&deg2, g_deg2);
    cudaGetSymbolAddress((void**)&inv0, g_inv0);
    cudaGetSymbolAddress((void**)&inv1, g_inv1);
    cudaGetSymbolAddress((void**)&inv2, g_inv2);
    cudaGetSymbolAddress((void**)&off0, g_off0);
    cudaGetSymbolAddress((void**)&off1, g_off1);
    cudaGetSymbolAddress((void**)&off2, g_off2);
    cudaGetSymbolAddress((void**)&cur0, g_cur0);
    cudaGetSymbolAddress((void**)&cur1, g_cur1);
    cudaGetSymbolAddress((void**)&cur2, g_cur2);
    cudaGetSymbolAddress((void**)&s0, g_srt0);
    cudaGetSymbolAddress((void**)&s1, g_srt1);
    cudaGetSymbolAddress((void**)&s2, g_srt2);

    // ---- degrees + CSR (rebuilt every launch: graph replays must be self-contained)
    cudaMemsetAsync(deg0, 0, N_NEWS * sizeof(int));
    cudaMemsetAsync(deg1, 0, N_INT  * sizeof(int));
    cudaMemsetAsync(deg2, 0, N_NEWS * sizeof(int));
    deg_kernel<<<(E0 + 255) / 256, 256>>>(e0d, E0, deg0);
    deg_kernel<<<(E1 + 255) / 256, 256>>>(e1d, E1, deg1);
    deg_kernel<<<(E2 + 255) / 256, 256>>>(e2d, E2, deg2);
    invdeg_kernel<<<(N_NEWS + 255) / 256, 256>>>(deg0, inv0, N_NEWS);
    invdeg_kernel<<<(N_INT  + 255) / 256, 256>>>(deg1, inv1, N_INT);
    invdeg_kernel<<<(N_NEWS + 255) / 256, 256>>>(deg2, inv2, N_NEWS);
    scan_kernel<<<1, 1024>>>(deg0, off0, N_NEWS);
    scan_kernel<<<1, 1024>>>(deg1, off1, N_INT);
    scan_kernel<<<1, 1024>>>(deg2, off2, N_NEWS);
    cudaMemcpyAsync(cur0, off0, N_NEWS * sizeof(int), cudaMemcpyDeviceToDevice);
    cudaMemcpyAsync(cur1, off1, N_INT  * sizeof(int), cudaMemcpyDeviceToDevice);
    cudaMemcpyAsync(cur2, off2, N_NEWS * sizeof(int), cudaMemcpyDeviceToDevice);
    fill_kernel<<<(E0 + 255) / 256, 256>>>(e0s, e0d, E0, 0,      cur0, s0);
    fill_kernel<<<(E1 + 255) / 256, 256>>>(e1s, e1d, E1, 0,      cur1, s1);
    fill_kernel<<<(E2 + 255) / 256, 256>>>(e2s, e2d, E2, N_NEWS, cur2, s2);

    // ---- encode: XA = [x_news@Wn+bn ; x_int@Wi+bi]
    sgemm_kernel<false><<<dim3(2, (N_NEWS + 127) / 128), 256>>>(
        x_news, F_IN, Wn, nullptr, bn, XA, N_NEWS, F_IN);
    sgemm_kernel<false><<<dim3(2, (N_INT + 127) / 128), 256>>>(
        x_int, F_IN, Wi, nullptr, bi, XA + (size_t)N_NEWS * H, N_INT, F_IN);

    const float* X = XA;
    float* Xn = XB;
    for (int l = 0; l < 2; l++) {
        // aggregation (dst ranges: rel0/rel2 -> news rows, rel1 -> interaction rows)
        aggregate_kernel<<<(N_NEWS * 32 + 255) / 256, 256>>>(X, off0, s0, inv0, A0, N_NEWS);
        aggregate_kernel<<<(N_INT  * 32 + 255) / 256, 256>>>(X, off1, s1, inv1, A1, N_INT);
        aggregate_kernel<<<(N_NEWS * 32 + 255) / 256, 256>>>(X, off2, s2, inv2, A2, N_NEWS);

        // O = X @ W_root[l] + conv_b[l]     (all 60000 rows)
        sgemm_kernel<false><<<dim3(2, (N_ALL + 127) / 128), 256>>>(
            X, H, W_root + (size_t)l * H * H, nullptr, conv_b + (size_t)l * H, O, N_ALL, H);
        // O[:10000] += A0 @ W_rel[l,0]
        sgemm_kernel<false><<<dim3(2, (N_NEWS + 127) / 128), 256>>>(
            A0, H, W_rel + (size_t)(l * 3 + 0) * H * H, O, nullptr, O, N_NEWS, H);
        // Xn[10000:] = relu(O[10000:] + A1 @ W_rel[l,1])
        sgemm_kernel<true><<<dim3(2, (N_INT + 127) / 128), 256>>>(
            A1, H, W_rel + (size_t)(l * 3 + 1) * H * H,
            O + (size_t)N_NEWS * H, nullptr, Xn + (size_t)N_NEWS * H, N_INT, H);
        // Xn[:10000] = relu(O[:10000] + A2 @ W_rel[l,2])
        sgemm_kernel<true><<<dim3(2, (N_NEWS + 127) / 128), 256>>>(
            A2, H, W_rel + (size_t)(l * 3 + 2) * H * H, O, nullptr, Xn, N_NEWS, H);

        const float* tmp = X;
        X = Xn;
        Xn = (float*)tmp;
    }

    // ---- final projection for news rows
    out_proj_kernel<<<(N_NEWS + 31) / 32, 256>>>(X, out_W, out_b, out);
}

// round 2
// speedup vs baseline: 1.0675x; 1.0675x over previous
#include <cuda_runtime.h>
#include <cuda_bf16.h>
#include <cstddef>

// Problem constants
#define N_NEWS 10000
#define N_INT  50000
#define N_ALL  60000
#define F_IN   768
#define H      256
#define OUTD   8

// ---------------- device scratch (no allocations allowed) ----------------
__device__ float g_XA[N_ALL * H];
__device__ float g_XB[N_ALL * H];
__device__ float g_O [N_ALL * H];
__device__ float g_A0[N_NEWS * H];
__device__ float g_A1[N_INT  * H];
__device__ float g_A2[N_NEWS * H];

__device__ int   g_deg0[N_NEWS], g_deg1[N_INT], g_deg2[N_NEWS];
__device__ float g_inv0[N_NEWS], g_inv1[N_INT], g_inv2[N_NEWS];
__device__ int   g_off0[N_NEWS + 1], g_off1[N_INT + 1], g_off2[N_NEWS + 1];
__device__ int   g_cur0[N_NEWS], g_cur1[N_INT], g_cur2[N_NEWS];
__device__ int   g_srt0[500000], g_srt1[400000], g_srt2[400000];

// ---------------- degree / inv-degree ----------------
__global__ void deg_kernel(const int* __restrict__ dst, int n, int* __restrict__ deg) {
    int i = blockIdx.x * blockDim.x + threadIdx.x;
    if (i < n) atomicAdd(&deg[dst[i]], 1);
}

__global__ void invdeg_kernel(const int* __restrict__ deg, float* __restrict__ inv, int n) {
    int i = blockIdx.x * blockDim.x + threadIdx.x;
    if (i < n) {
        int d = deg[i];
        inv[i] = (d > 0) ? (1.0f / (float)d) : 0.0f;
    }
}

// ---------------- single-block chunked exclusive scan (2 barriers total) ---
// Each of 1024 threads owns a contiguous chunk; shfl-scan the thread sums.
// Writes both off[] and cur[] (so no memcpy needed afterwards).
__global__ __launch_bounds__(1024) void scan_kernel(const int* __restrict__ deg,
                                                    int* __restrict__ off,
                                                    int* __restrict__ cur, int n) {
    __shared__ int warpsum[32];
    const int t = (int)threadIdx.x;
    const int CH = (n + 1023) >> 10;
    const int start = t * CH;

    int local = 0;
    for (int c = 0; c < CH; c++) {
        int i = start + c;
        if (i < n) local += deg[i];
    }
    int lane = t & 31, w = t >> 5;
    int v = local;
    #pragma unroll
    for (int s = 1; s < 32; s <<= 1) {
        int u = __shfl_up_sync(0xFFFFFFFFu, v, s);
        if (lane >= s) v += u;
    }
    if (lane == 31) warpsum[w] = v;
    __syncthreads();
    if (w == 0) {
        int ws = warpsum[lane];
        #pragma unroll
        for (int s = 1; s < 32; s <<= 1) {
            int u = __shfl_up_sync(0xFFFFFFFFu, ws, s);
            if (lane >= s) ws += u;
        }
        warpsum[lane] = ws;
    }
    __syncthreads();
    int prefix = (v - local) + (w > 0 ? warpsum[w - 1] : 0);
    int run = prefix;
    for (int c = 0; c < CH; c++) {
        int i = start + c;
        if (i < n) {
            off[i] = run;
            cur[i] = run;
            run += deg[i];
        }
    }
    if (t == 1023) off[n] = run;
}

// ---------------- CSR fill (src stored as GLOBAL node index) ----------------
__global__ void fill_kernel(const int* __restrict__ src, const int* __restrict__ dst,
                            int n, int srcOffset,
                            int* __restrict__ cur, int* __restrict__ srt) {
    int i = blockIdx.x * blockDim.x + threadIdx.x;
    if (i < n) {
        int p = atomicAdd(&cur[dst[i]], 1);
        srt[p] = src[i] + srcOffset;
    }
}

// ---------------- warp-per-node mean aggregation (gather, no atomics) ------
__global__ void aggregate_kernel(const float* __restrict__ X,
                                 const int* __restrict__ off,
                                 const int* __restrict__ srt,
                                 const float* __restrict__ invdeg,
                                 float* __restrict__ out, int count) {
    int gw   = (int)((blockIdx.x * blockDim.x + threadIdx.x) >> 5);
    int lane = threadIdx.x & 31;
    if (gw >= count) return;
    int e0 = off[gw], e1 = off[gw + 1];
    float4 s0 = make_float4(0.f, 0.f, 0.f, 0.f);
    float4 s1 = make_float4(0.f, 0.f, 0.f, 0.f);
    for (int e = e0; e < e1; e++) {
        int src = srt[e];
        const float4* row = (const float4*)(X + (size_t)src * H);
        float4 v0 = __ldg(&row[lane]);
        float4 v1 = __ldg(&row[lane + 32]);
        s0.x += v0.x; s0.y += v0.y; s0.z += v0.z; s0.w += v0.w;
        s1.x += v1.x; s1.y += v1.y; s1.z += v1.z; s1.w += v1.w;
    }
    float d = invdeg[gw];
    s0.x *= d; s0.y *= d; s0.z *= d; s0.w *= d;
    s1.x *= d; s1.y *= d; s1.z *= d; s1.w *= d;
    float4* o = (float4*)(out + (size_t)gw * H);
    o[lane]      = s0;
    o[lane + 32] = s1;
}

// ---------------- tiled SGEMM with packed fma.rn.f32x2 --------------------
// C = A(MxK) * B(Kx256) [+Cin|+bias] [relu].  N fixed 256, ldb/ldc = 256.
// Accumulators are f32x2 pairs over the column dimension: 2x fp32 FMA/issue.
template <bool RELU>
__global__ __launch_bounds__(256) void sgemm_kernel(
    const float* __restrict__ A, int lda,
    const float* __restrict__ B,
    const float* __restrict__ Cin,
    const float* __restrict__ bias,
    float* __restrict__ Cout,
    int M, int K) {
    constexpr int BM = 128, BN = 128, BK = 8;
    __shared__ float As[BK][BM];
    __shared__ float Bs[BK][BN];

    const int tid  = threadIdx.x;
    const int row0 = blockIdx.y * BM;
    const int col0 = blockIdx.x * BN;

    const int aRow = tid >> 1;
    const int aCol = (tid & 1) << 2;
    const int bRow = tid >> 5;
    const int bCol = (tid & 31) << 2;

    const int ty = (tid >> 4) << 3;  // 0..120
    const int tx = (tid & 15) << 3;  // 0..120

    unsigned long long acc2[8][4];   // pair (col 2jp, 2jp+1) for row i
    #pragma unroll
    for (int i = 0; i < 8; i++)
        #pragma unroll
        for (int jp = 0; jp < 4; jp++) acc2[i][jp] = 0ULL;

    const bool  aValid = (row0 + aRow) < M;
    const float* Aptr  = A + (size_t)(row0 + aRow) * lda + aCol;
    const float* Bptr  = B + (size_t)bRow * H + col0 + bCol;

    for (int k0 = 0; k0 < K; k0 += BK) {
        float4 av = aValid ? *(const float4*)(Aptr + k0)
                           : make_float4(0.f, 0.f, 0.f, 0.f);
        float4 bv = *(const float4*)(Bptr + (size_t)k0 * H);
        As[aCol + 0][aRow] = av.x;
        As[aCol + 1][aRow] = av.y;
        As[aCol + 2][aRow] = av.z;
        As[aCol + 3][aRow] = av.w;
        *(float4*)&Bs[bRow][bCol] = bv;
        __syncthreads();

        #pragma unroll
        for (int k = 0; k < BK; k++) {
            float4 a0 = *(const float4*)&As[k][ty];
            float4 a1 = *(const float4*)&As[k][ty + 4];
            float a[8] = {a0.x, a0.y, a0.z, a0.w, a1.x, a1.y, a1.z, a1.w};
            const unsigned long long* brow = (const unsigned long long*)&Bs[k][tx];
            unsigned long long bp0 = brow[0], bp1 = brow[1], bp2 = brow[2], bp3 = brow[3];
            #pragma unroll
            for (int i = 0; i < 8; i++) {
                unsigned long long aa;
                asm("mov.b64 %0, {%1, %1};" : "=l"(aa) : "f"(a[i]));
                asm("fma.rn.f32x2 %0, %1, %2, %0;" : "+l"(acc2[i][0]) : "l"(aa), "l"(bp0));
                asm("fma.rn.f32x2 %0, %1, %2, %0;" : "+l"(acc2[i][1]) : "l"(aa), "l"(bp1));
                asm("fma.rn.f32x2 %0, %1, %2, %0;" : "+l"(acc2[i][2]) : "l"(aa), "l"(bp2));
                asm("fma.rn.f32x2 %0, %1, %2, %0;" : "+l"(acc2[i][3]) : "l"(aa), "l"(bp3));
            }
        }
        __syncthreads();
    }

    #pragma unroll
    for (int i = 0; i < 8; i++) {
        int r = row0 + ty + i;
        if (r < M) {
            float c[8];
            #pragma unroll
            for (int jp = 0; jp < 4; jp++) {
                union { unsigned long long u; float2 f; } cv;
                cv.u = acc2[i][jp];
                c[2 * jp]     = cv.f.x;
                c[2 * jp + 1] = cv.f.y;
            }
            #pragma unroll
            for (int j = 0; j < 8; j += 4) {
                int col = col0 + tx + j;
                float4 v = make_float4(c[j], c[j + 1], c[j + 2], c[j + 3]);
                if (Cin) {
                    float4 ci = *(const float4*)(Cin + (size_t)r * H + col);
                    v.x += ci.x; v.y += ci.y; v.z += ci.z; v.w += ci.w;
                }
                if (bias) {
                    float4 bb = *(const float4*)(bias + col);
                    v.x += bb.x; v.y += bb.y; v.z += bb.z; v.w += bb.w;
                }
                if (RELU) {
                    v.x = fmaxf(v.x, 0.f); v.y = fmaxf(v.y, 0.f);
                    v.z = fmaxf(v.z, 0.f); v.w = fmaxf(v.w, 0.f);
                }
                *(float4*)(Cout + (size_t)r * H + col) = v;
            }
        }
    }
}

// ---------------- final projection: out = X[:10000] @ W(256x8) + b --------
__global__ void out_proj_kernel(const float* __restrict__ X,
                                const float* __restrict__ W,
                                const float* __restrict__ b,
                                float* __restrict__ out) {
    int i = blockIdx.x * 32 + (threadIdx.x >> 3);
    int o = threadIdx.x & 7;
    if (i >= N_NEWS) return;
    float s = b[o];
    const float* x = X + (size_t)i * H;
    #pragma unroll 8
    for (int j = 0; j < H; j++) s += x[j] * __ldg(&W[j * OUTD + o]);
    out[i * OUTD + o] = s;
}

// ---------------- launch ----------------
extern "C" void kernel_launch(void* const* d_in, const int* in_sizes, int n_in,
                              void* d_out, int out_size) {
    const float* x_news = (const float*)d_in[0];
    const float* x_int  = (const float*)d_in[1];
    const float* Wn     = (const float*)d_in[2];
    const float* bn     = (const float*)d_in[3];
    const float* Wi     = (const float*)d_in[4];
    const float* bi     = (const float*)d_in[5];
    const float* W_rel  = (const float*)d_in[6];
    const float* W_root = (const float*)d_in[7];
    const float* conv_b = (const float*)d_in[8];
    const float* out_W  = (const float*)d_in[9];
    const float* out_b  = (const float*)d_in[10];
    const int* e0s = (const int*)d_in[11];
    const int* e0d = (const int*)d_in[12];
    const int* e1s = (const int*)d_in[13];
    const int* e1d = (const int*)d_in[14];
    const int* e2s = (const int*)d_in[15];
    const int* e2d = (const int*)d_in[16];
    const int E0 = in_sizes[11], E1 = in_sizes[13], E2 = in_sizes[15];
    float* out = (float*)d_out;

    float *XA, *XB, *O, *A0, *A1, *A2, *inv0, *inv1, *inv2;
    int *deg0, *deg1, *deg2, *off0, *off1, *off2, *cur0, *cur1, *cur2, *s0, *s1, *s2;
    cudaGetSymbolAddress((void**)&XA, g_XA);
    cudaGetSymbolAddress((void**)&XB, g_XB);
    cudaGetSymbolAddress((void**)&O,  g_O);
    cudaGetSymbolAddress((void**)&A0, g_A0);
    cudaGetSymbolAddress((void**)&A1, g_A1);
    cudaGetSymbolAddress((void**)&A2, g_A2);
    cudaGetSymbolAddress((void**)&deg0, g_deg0);
    cudaGetSymbolAddress((void**)&deg1, g_deg1);
    cudaGetSymbolAddress((void**)&deg2, g_deg2);
    cudaGetSymbolAddress((void**)&inv0, g_inv0);
    cudaGetSymbolAddress((void**)&inv1, g_inv1);
    cudaGetSymbolAddress((void**)&inv2, g_inv2);
    cudaGetSymbolAddress((void**)&off0, g_off0);
    cudaGetSymbolAddress((void**)&off1, g_off1);
    cudaGetSymbolAddress((void**)&off2, g_off2);
    cudaGetSymbolAddress((void**)&cur0, g_cur0);
    cudaGetSymbolAddress((void**)&cur1, g_cur1);
    cudaGetSymbolAddress((void**)&cur2, g_cur2);
    cudaGetSymbolAddress((void**)&s0, g_srt0);
    cudaGetSymbolAddress((void**)&s1, g_srt1);
    cudaGetSymbolAddress((void**)&s2, g_srt2);

    // ---- degrees + CSR (rebuilt every launch: graph replays must be self-contained)
    cudaMemsetAsync(deg0, 0, N_NEWS * sizeof(int));
    cudaMemsetAsync(deg1, 0, N_INT  * sizeof(int));
    cudaMemsetAsync(deg2, 0, N_NEWS * sizeof(int));
    deg_kernel<<<(E0 + 255) / 256, 256>>>(e0d, E0, deg0);
    deg_kernel<<<(E1 + 255) / 256, 256>>>(e1d, E1, deg1);
    deg_kernel<<<(E2 + 255) / 256, 256>>>(e2d, E2, deg2);
    invdeg_kernel<<<(N_NEWS + 255) / 256, 256>>>(deg0, inv0, N_NEWS);
    invdeg_kernel<<<(N_INT  + 255) / 256, 256>>>(deg1, inv1, N_INT);
    invdeg_kernel<<<(N_NEWS + 255) / 256, 256>>>(deg2, inv2, N_NEWS);
    scan_kernel<<<1, 1024>>>(deg0, off0, cur0, N_NEWS);
    scan_kernel<<<1, 1024>>>(deg1, off1, cur1, N_INT);
    scan_kernel<<<1, 1024>>>(deg2, off2, cur2, N_NEWS);
    fill_kernel<<<(E0 + 255) / 256, 256>>>(e0s, e0d, E0, 0,      cur0, s0);
    fill_kernel<<<(E1 + 255) / 256, 256>>>(e1s, e1d, E1, 0,      cur1, s1);
    fill_kernel<<<(E2 + 255) / 256, 256>>>(e2s, e2d, E2, N_NEWS, cur2, s2);

    // ---- encode: XA = [x_news@Wn+bn ; x_int@Wi+bi]
    sgemm_kernel<false><<<dim3(2, (N_NEWS + 127) / 128), 256>>>(
        x_news, F_IN, Wn, nullptr, bn, XA, N_NEWS, F_IN);
    sgemm_kernel<false><<<dim3(2, (N_INT + 127) / 128), 256>>>(
        x_int, F_IN, Wi, nullptr, bi, XA + (size_t)N_NEWS * H, N_INT, F_IN);

    const float* X = XA;
    float* Xn = XB;
    for (int l = 0; l < 2; l++) {
        // aggregation (dst ranges: rel0/rel2 -> news rows, rel1 -> interaction rows)
        aggregate_kernel<<<(N_NEWS * 32 + 255) / 256, 256>>>(X, off0, s0, inv0, A0, N_NEWS);
        aggregate_kernel<<<(N_INT  * 32 + 255) / 256, 256>>>(X, off1, s1, inv1, A1, N_INT);
        aggregate_kernel<<<(N_NEWS * 32 + 255) / 256, 256>>>(X, off2, s2, inv2, A2, N_NEWS);

        // O = X @ W_root[l] + conv_b[l]     (all 60000 rows)
        sgemm_kernel<false><<<dim3(2, (N_ALL + 127) / 128), 256>>>(
            X, H, W_root + (size_t)l * H * H, nullptr, conv_b + (size_t)l * H, O, N_ALL, H);
        // O[:10000] += A0 @ W_rel[l,0]
        sgemm_kernel<false><<<dim3(2, (N_NEWS + 127) / 128), 256>>>(
            A0, H, W_rel + (size_t)(l * 3 + 0) * H * H, O, nullptr, O, N_NEWS, H);
        // Xn[10000:] = relu(O[10000:] + A1 @ W_rel[l,1])
        sgemm_kernel<true><<<dim3(2, (N_INT + 127) / 128), 256>>>(
            A1, H, W_rel + (size_t)(l * 3 + 1) * H * H,
            O + (size_t)N_NEWS * H, nullptr, Xn + (size_t)N_NEWS * H, N_INT, H);
        // Xn[:10000] = relu(O[:10000] + A2 @ W_rel[l,2])
        sgemm_kernel<true><<<dim3(2, (N_NEWS + 127) / 128), 256>>>(
            A2, H, W_rel + (size_t)(l * 3 + 2) * H * H, O, nullptr, Xn, N_NEWS, H);

        const float* tmp = X;
        X = Xn;
        Xn = (float*)tmp;
    }

    // ---- final projection for news rows
    out_proj_kernel<<<(N_NEWS + 31) / 32, 256>>>(X, out_W, out_b, out);
}

// round 5
// speedup vs baseline: 1.8001x; 1.6863x over previous
#include <cuda_runtime.h>
#include <cuda_bf16.h>
#include <cstdint>
#include <cstddef>

// Problem constants
#define N_NEWS 10000
#define N_INT  50000
#define N_ALL  60000
#define F_IN   768
#define H      256
#define OUTD   8

// ---------------- device scratch (no allocations allowed) ----------------
__device__ float g_XA[N_ALL * H];
__device__ float g_XB[N_ALL * H];
__device__ float g_O [N_ALL * H];
__device__ float g_A0[N_NEWS * H];
__device__ float g_A1[N_INT  * H];
__device__ float g_A2[N_NEWS * H];

__device__ int   g_deg0[N_NEWS], g_deg1[N_INT], g_deg2[N_NEWS];
__device__ float g_inv0[N_NEWS], g_inv1[N_INT], g_inv2[N_NEWS];
__device__ int   g_off0[N_NEWS + 1], g_off1[N_INT + 1], g_off2[N_NEWS + 1];
__device__ int   g_cur0[N_NEWS], g_cur1[N_INT], g_cur2[N_NEWS];
__device__ int   g_srt0[500000], g_srt1[400000], g_srt2[400000];

// Transposed/split weights: [N=256 rows][K cols] bf16, hi and lo parts.
#define WOFF_WN   0
#define WOFF_WI   196608
#define WOFF_ROOT 393216
#define WOFF_REL  524288
#define WTOTAL    917504
__device__ __nv_bfloat16 g_Bhi[WTOTAL];
__device__ __nv_bfloat16 g_Blo[WTOTAL];

// ================= helpers =================
__device__ __forceinline__ uint32_t smem_u32(const void* p) {
    uint32_t a;
    asm("{ .reg .u64 t; cvta.to.shared.u64 t, %1; cvt.u32.u64 %0, t; }" : "=r"(a) : "l"(p));
    return a;
}
__device__ __forceinline__ uint32_t pack_bf2(__nv_bfloat16 a, __nv_bfloat16 b) {
    return (uint32_t)__bfloat16_as_ushort(a) | ((uint32_t)__bfloat16_as_ushort(b) << 16);
}
__device__ __forceinline__ void ldm_x4(uint32_t& r0, uint32_t& r1, uint32_t& r2, uint32_t& r3,
                                       uint32_t addr) {
    asm volatile("ldmatrix.sync.aligned.m8n8.x4.shared.b16 {%0,%1,%2,%3}, [%4];"
                 : "=r"(r0), "=r"(r1), "=r"(r2), "=r"(r3) : "r"(addr));
}
__device__ __forceinline__ void mma_bf16(float* c, uint32_t a0, uint32_t a1, uint32_t a2,
                                         uint32_t a3, uint32_t b0, uint32_t b1) {
    asm volatile("mma.sync.aligned.m16n8k16.row.col.f32.bf16.bf16.f32 "
                 "{%0,%1,%2,%3}, {%4,%5,%6,%7}, {%8,%9}, {%0,%1,%2,%3};"
                 : "+f"(c[0]), "+f"(c[1]), "+f"(c[2]), "+f"(c[3])
                 : "r"(a0), "r"(a1), "r"(a2), "r"(a3), "r"(b0), "r"(b1));
}

// ================= HMMA GEMM (3-term bf16 split) =================
// C[M,256] = A[M,K](fp32) @ B[K,256]; B given pre-transposed/split as [256][K] bf16.
// Block: 128(M) x 128(N), BK=32, 256 threads = 8 warps (4m x 2n), warp tile 32x64.
#define BKP 40   // padded row length (bf16 elems): 80 bytes, conflict-free for ldmatrix

template <bool RELU>
__global__ __launch_bounds__(256) void mma_gemm_kernel(
    const float* __restrict__ A,
    const __nv_bfloat16* __restrict__ Bth,
    const __nv_bfloat16* __restrict__ Btl,
    const float* __restrict__ Cin,
    const float* __restrict__ bias,
    float* __restrict__ Cout,
    int M, int K) {
    __shared__ __nv_bfloat16 sAh[128][BKP];
    __shared__ __nv_bfloat16 sAl[128][BKP];
    __shared__ __nv_bfloat16 sBh[128][BKP];
    __shared__ __nv_bfloat16 sBl[128][BKP];

    const int tid  = threadIdx.x;
    const int wid  = tid >> 5;
    const int lane = tid & 31;
    const int wm   = wid & 3;          // 0..3 -> m offset wm*32
    const int wn   = wid >> 2;         // 0..1 -> n offset wn*64
    const int row0 = blockIdx.y * 128;
    const int col0 = blockIdx.x * 128;

    const uint32_t sAh0 = smem_u32(&sAh[0][0]);
    const uint32_t sAl0 = smem_u32(&sAl[0][0]);
    const uint32_t sBh0 = smem_u32(&sBh[0][0]);
    const uint32_t sBl0 = smem_u32(&sBl[0][0]);

    float acc[2][8][4];
    #pragma unroll
    for (int i = 0; i < 2; i++)
        #pragma unroll
        for (int j = 0; j < 8; j++)
            #pragma unroll
            for (int q = 0; q < 4; q++) acc[i][j][q] = 0.f;

    // fill mapping: 2 threads per row, each covers 16 elems
    const int fRow  = tid >> 1;
    const int fHalf = tid & 1;

    for (int k0 = 0; k0 < K; k0 += 32) {
        // ---- A tile: 128x32 fp32 -> bf16 hi/lo ----
        {
            const int r = row0 + fRow;
            const float* ap = A + (size_t)r * K + k0 + fHalf * 16;
            uint32_t* dh = (uint32_t*)&sAh[fRow][fHalf * 16];
            uint32_t* dl = (uint32_t*)&sAl[fRow][fHalf * 16];
            #pragma unroll
            for (int j = 0; j < 4; j++) {
                float4 v = (r < M) ? *(const float4*)(ap + j * 4)
                                   : make_float4(0.f, 0.f, 0.f, 0.f);
                __nv_bfloat16 hx = __float2bfloat16(v.x), hy = __float2bfloat16(v.y);
                __nv_bfloat16 hz = __float2bfloat16(v.z), hw = __float2bfloat16(v.w);
                dh[2 * j]     = pack_bf2(hx, hy);
                dh[2 * j + 1] = pack_bf2(hz, hw);
                dl[2 * j]     = pack_bf2(__float2bfloat16(v.x - __bfloat162float(hx)),
                                         __float2bfloat16(v.y - __bfloat162float(hy)));
                dl[2 * j + 1] = pack_bf2(__float2bfloat16(v.z - __bfloat162float(hz)),
                                         __float2bfloat16(v.w - __bfloat162float(hw)));
            }
        }
        // ---- B tile: rows n = col0+fRow, 32 bf16 each of hi/lo ----
        {
            const size_t gidx = (size_t)(col0 + fRow) * K + k0 + fHalf * 16;
            uint4 h0 = *(const uint4*)(Bth + gidx);
            uint4 h1 = *(const uint4*)(Bth + gidx + 8);
            uint4 l0 = *(const uint4*)(Btl + gidx);
            uint4 l1 = *(const uint4*)(Btl + gidx + 8);
            uint4* dh = (uint4*)&sBh[fRow][fHalf * 16];
            uint4* dl = (uint4*)&sBl[fRow][fHalf * 16];
            dh[0] = h0; dh[1] = h1;
            dl[0] = l0; dl[1] = l1;
        }
        __syncthreads();

        #pragma unroll
        for (int kk = 0; kk < 2; kk++) {
            // A fragments (hi & lo) for 2 m16 tiles
            uint32_t ah[2][4], al[2][4];
            #pragma unroll
            for (int mt = 0; mt < 2; mt++) {
                const uint32_t roff =
                    (uint32_t)(wm * 32 + mt * 16 + ((lane >> 3) & 1) * 8 + (lane & 7)) * (BKP * 2)
                    + kk * 32 + (lane >> 4) * 16;
                ldm_x4(ah[mt][0], ah[mt][1], ah[mt][2], ah[mt][3], sAh0 + roff);
                ldm_x4(al[mt][0], al[mt][1], al[mt][2], al[mt][3], sAl0 + roff);
            }
            #pragma unroll
            for (int ng = 0; ng < 4; ng++) {
                const uint32_t boff =
                    (uint32_t)(wn * 64 + ng * 16 + ((lane >> 4) & 1) * 8 + (lane & 7)) * (BKP * 2)
                    + kk * 32 + ((lane >> 3) & 1) * 16;
                uint32_t bh[4], bl[4];
                ldm_x4(bh[0], bh[1], bh[2], bh[3], sBh0 + boff);
                ldm_x4(bl[0], bl[1], bl[2], bl[3], sBl0 + boff);
                #pragma unroll
                for (int mt = 0; mt < 2; mt++) {
                    #pragma unroll
                    for (int h = 0; h < 2; h++) {
                        float* c = acc[mt][ng * 2 + h];
                        mma_bf16(c, ah[mt][0], ah[mt][1], ah[mt][2], ah[mt][3],
                                 bh[2 * h], bh[2 * h + 1]);
                        mma_bf16(c, ah[mt][0], ah[mt][1], ah[mt][2], ah[mt][3],
                                 bl[2 * h], bl[2 * h + 1]);
                        mma_bf16(c, al[mt][0], al[mt][1], al[mt][2], al[mt][3],
                                 bh[2 * h], bh[2 * h + 1]);
                    }
                }
            }
        }
        __syncthreads();
    }

    // ---- epilogue ----
    const int colBase = col0 + wn * 64 + (lane & 3) * 2;
    #pragma unroll
    for (int mt = 0; mt < 2; mt++) {
        #pragma unroll
        for (int half = 0; half < 2; half++) {
            const int r = row0 + wm * 32 + mt * 16 + (lane >> 2) + half * 8;
            if (r < M) {
                #pragma unroll
                for (int nt = 0; nt < 8; nt++) {
                    const int c = colBase + nt * 8;
                    float v0 = acc[mt][nt][2 * half];
                    float v1 = acc[mt][nt][2 * half + 1];
                    if (Cin) {
                        const float2 ci = *(const float2*)(Cin + (size_t)r * H + c);
                        v0 += ci.x; v1 += ci.y;
                    }
                    if (bias) {
                        const float2 bb = *(const float2*)(bias + c);
                        v0 += bb.x; v1 += bb.y;
                    }
                    if (RELU) { v0 = fmaxf(v0, 0.f); v1 = fmaxf(v1, 0.f); }
                    *(float2*)(Cout + (size_t)r * H + c) = make_float2(v0, v1);
                }
            }
        }
    }
}

// ---------------- weight transpose + bf16 hi/lo split ----------------
__global__ void wprep_kernel(const float* __restrict__ W, int K,
                             __nv_bfloat16* __restrict__ Bth,
                             __nv_bfloat16* __restrict__ Btl) {
    int idx = blockIdx.x * blockDim.x + threadIdx.x;
    if (idx >= K * 256) return;
    int k = idx >> 8;
    int n = idx & 255;
    float v = W[idx];
    __nv_bfloat16 h = __float2bfloat16(v);
    Bth[(size_t)n * K + k] = h;
    Btl[(size_t)n * K + k] = __float2bfloat16(v - __bfloat162float(h));
}

// ---------------- degree / inv-degree ----------------
__global__ void deg_kernel(const int* __restrict__ dst, int n, int* __restrict__ deg) {
    int i = blockIdx.x * blockDim.x + threadIdx.x;
    if (i < n) atomicAdd(&deg[dst[i]], 1);
}

__global__ void invdeg_kernel(const int* __restrict__ deg, float* __restrict__ inv, int n) {
    int i = blockIdx.x * blockDim.x + threadIdx.x;
    if (i < n) {
        int d = deg[i];
        inv[i] = (d > 0) ? (1.0f / (float)d) : 0.0f;
    }
}

// ---------------- single-block chunked exclusive scan ----------------
__global__ __launch_bounds__(1024) void scan_kernel(const int* __restrict__ deg,
                                                    int* __restrict__ off,
                                                    int* __restrict__ cur, int n) {
    __shared__ int warpsum[32];
    const int t = (int)threadIdx.x;
    const int CH = (n + 1023) >> 10;
    const int start = t * CH;

    int local = 0;
    for (int c = 0; c < CH; c++) {
        int i = start + c;
        if (i < n) local += deg[i];
    }
    int lane = t & 31, w = t >> 5;
    int v = local;
    #pragma unroll
    for (int s = 1; s < 32; s <<= 1) {
        int u = __shfl_up_sync(0xFFFFFFFFu, v, s);
        if (lane >= s) v += u;
    }
    if (lane == 31) warpsum[w] = v;
    __syncthreads();
    if (w == 0) {
        int ws = warpsum[lane];
        #pragma unroll
        for (int s = 1; s < 32; s <<= 1) {
            int u = __shfl_up_sync(0xFFFFFFFFu, ws, s);
            if (lane >= s) ws += u;
        }
        warpsum[lane] = ws;
    }
    __syncthreads();
    int prefix = (v - local) + (w > 0 ? warpsum[w - 1] : 0);
    int run = prefix;
    for (int c = 0; c < CH; c++) {
        int i = start + c;
        if (i < n) {
            off[i] = run;
            cur[i] = run;
            run += deg[i];
        }
    }
    if (t == 1023) off[n] = run;
}

// ---------------- CSR fill ----------------
__global__ void fill_kernel(const int* __restrict__ src, const int* __restrict__ dst,
                            int n, int srcOffset,
                            int* __restrict__ cur, int* __restrict__ srt) {
    int i = blockIdx.x * blockDim.x + threadIdx.x;
    if (i < n) {
        int p = atomicAdd(&cur[dst[i]], 1);
        srt[p] = src[i] + srcOffset;
    }
}

// ---------------- warp-per-node mean aggregation ----------------
__global__ void aggregate_kernel(const float* __restrict__ X,
                                 const int* __restrict__ off,
                                 const int* __restrict__ srt,
                                 const float* __restrict__ invdeg,
                                 float* __restrict__ out, int count) {
    int gw   = (int)((blockIdx.x * blockDim.x + threadIdx.x) >> 5);
    int lane = threadIdx.x & 31;
    if (gw >= count) return;
    int e0 = off[gw], e1 = off[gw + 1];
    float4 s0 = make_float4(0.f, 0.f, 0.f, 0.f);
    float4 s1 = make_float4(0.f, 0.f, 0.f, 0.f);
    for (int e = e0; e < e1; e++) {
        int src = srt[e];
        const float4* row = (const float4*)(X + (size_t)src * H);
        float4 v0 = __ldg(&row[lane]);
        float4 v1 = __ldg(&row[lane + 32]);
        s0.x += v0.x; s0.y += v0.y; s0.z += v0.z; s0.w += v0.w;
        s1.x += v1.x; s1.y += v1.y; s1.z += v1.z; s1.w += v1.w;
    }
    float d = invdeg[gw];
    s0.x *= d; s0.y *= d; s0.z *= d; s0.w *= d;
    s1.x *= d; s1.y *= d; s1.z *= d; s1.w *= d;
    float4* o = (float4*)(out + (size_t)gw * H);
    o[lane]      = s0;
    o[lane + 32] = s1;
}

// ---------------- final projection ----------------
__global__ void out_proj_kernel(const float* __restrict__ X,
                                const float* __restrict__ W,
                                const float* __restrict__ b,
                                float* __restrict__ out) {
    int i = blockIdx.x * 32 + (threadIdx.x >> 3);
    int o = threadIdx.x & 7;
    if (i >= N_NEWS) return;
    float s = b[o];
    const float* x = X + (size_t)i * H;
    #pragma unroll 8
    for (int j = 0; j < H; j++) s += x[j] * __ldg(&W[j * OUTD + o]);
    out[i * OUTD + o] = s;
}

// ---------------- launch ----------------
extern "C" void kernel_launch(void* const* d_in, const int* in_sizes, int n_in,
                              void* d_out, int out_size) {
    const float* x_news = (const float*)d_in[0];
    const float* x_int  = (const float*)d_in[1];
    const float* Wn     = (const float*)d_in[2];
    const float* bn     = (const float*)d_in[3];
    const float* Wi     = (const float*)d_in[4];
    const float* bi     = (const float*)d_in[5];
    const float* W_rel  = (const float*)d_in[6];
    const float* W_root = (const float*)d_in[7];
    const float* conv_b = (const float*)d_in[8];
    const float* out_W  = (const float*)d_in[9];
    const float* out_b  = (const float*)d_in[10];
    const int* e0s = (const int*)d_in[11];
    const int* e0d = (const int*)d_in[12];
    const int* e1s = (const int*)d_in[13];
    const int* e1d = (const int*)d_in[14];
    const int* e2s = (const int*)d_in[15];
    const int* e2d = (const int*)d_in[16];
    const int E0 = in_sizes[11], E1 = in_sizes[13], E2 = in_sizes[15];
    float* out = (float*)d_out;

    float *XA, *XB, *O, *A0, *A1, *A2, *inv0, *inv1, *inv2;
    int *deg0, *deg1, *deg2, *off0, *off1, *off2, *cur0, *cur1, *cur2, *s0, *s1, *s2;
    __nv_bfloat16 *Bhi, *Blo;
    cudaGetSymbolAddress((void**)&XA, g_XA);
    cudaGetSymbolAddress((void**)&XB, g_XB);
    cudaGetSymbolAddress((void**)&O,  g_O);
    cudaGetSymbolAddress((void**)&A0, g_A0);
    cudaGetSymbolAddress((void**)&A1, g_A1);
    cudaGetSymbolAddress((void**)&A2, g_A2);
    cudaGetSymbolAddress((void**)&deg0, g_deg0);
    cudaGetSymbolAddress((void**)&deg1, g_deg1);
    cudaGetSymbolAddress((void**)&deg2, g_deg2);
    cudaGetSymbolAddress((void**)&inv0, g_inv0);
    cudaGetSymbolAddress((void**)&inv1, g_inv1);
    cudaGetSymbolAddress((void**)&inv2, g_inv2);
    cudaGetSymbolAddress((void**)&off0, g_off0);
    cudaGetSymbolAddress((void**)&off1, g_off1);
    cudaGetSymbolAddress((void**)&off2, g_off2);
    cudaGetSymbolAddress((void**)&cur0, g_cur0);
    cudaGetSymbolAddress((void**)&cur1, g_cur1);
    cudaGetSymbolAddress((void**)&cur2, g_cur2);
    cudaGetSymbolAddress((void**)&s0, g_srt0);
    cudaGetSymbolAddress((void**)&s1, g_srt1);
    cudaGetSymbolAddress((void**)&s2, g_srt2);
    cudaGetSymbolAddress((void**)&Bhi, g_Bhi);
    cudaGetSymbolAddress((void**)&Blo, g_Blo);

    // ---- weight prep: transpose + bf16 split
    wprep_kernel<<<(F_IN * 256 + 255) / 256, 256>>>(Wn, F_IN, Bhi + WOFF_WN, Blo + WOFF_WN);
    wprep_kernel<<<(F_IN * 256 + 255) / 256, 256>>>(Wi, F_IN, Bhi + WOFF_WI, Blo + WOFF_WI);
    for (int l = 0; l < 2; l++) {
        wprep_kernel<<<(H * 256 + 255) / 256, 256>>>(
            W_root + (size_t)l * H * H, H, Bhi + WOFF_ROOT + l * 65536, Blo + WOFF_ROOT + l * 65536);
        for (int r = 0; r < 3; r++) {
            wprep_kernel<<<(H * 256 + 255) / 256, 256>>>(
                W_rel + (size_t)(l * 3 + r) * H * H, H,
                Bhi + WOFF_REL + (l * 3 + r) * 65536, Blo + WOFF_REL + (l * 3 + r) * 65536);
        }
    }

    // ---- degrees + CSR
    cudaMemsetAsync(deg0, 0, N_NEWS * sizeof(int));
    cudaMemsetAsync(deg1, 0, N_INT  * sizeof(int));
    cudaMemsetAsync(deg2, 0, N_NEWS * sizeof(int));
    deg_kernel<<<(E0 + 255) / 256, 256>>>(e0d, E0, deg0);
    deg_kernel<<<(E1 + 255) / 256, 256>>>(e1d, E1, deg1);
    deg_kernel<<<(E2 + 255) / 256, 256>>>(e2d, E2, deg2);
    invdeg_kernel<<<(N_NEWS + 255) / 256, 256>>>(deg0, inv0, N_NEWS);
    invdeg_kernel<<<(N_INT  + 255) / 256, 256>>>(deg1, inv1, N_INT);
    invdeg_kernel<<<(N_NEWS + 255) / 256, 256>>>(deg2, inv2, N_NEWS);
    scan_kernel<<<1, 1024>>>(deg0, off0, cur0, N_NEWS);
    scan_kernel<<<1, 1024>>>(deg1, off1, cur1, N_INT);
    scan_kernel<<<1, 1024>>>(deg2, off2, cur2, N_NEWS);
    fill_kernel<<<(E0 + 255) / 256, 256>>>(e0s, e0d, E0, 0,      cur0, s0);
    fill_kernel<<<(E1 + 255) / 256, 256>>>(e1s, e1d, E1, 0,      cur1, s1);
    fill_kernel<<<(E2 + 255) / 256, 256>>>(e2s, e2d, E2, N_NEWS, cur2, s2);

    // ---- encode: XA = [x_news@Wn+bn ; x_int@Wi+bi]
    mma_gemm_kernel<false><<<dim3(2, (N_NEWS + 127) / 128), 256>>>(
        x_news, Bhi + WOFF_WN, Blo + WOFF_WN, nullptr, bn, XA, N_NEWS, F_IN);
    mma_gemm_kernel<false><<<dim3(2, (N_INT + 127) / 128), 256>>>(
        x_int, Bhi + WOFF_WI, Blo + WOFF_WI, nullptr, bi, XA + (size_t)N_NEWS * H, N_INT, F_IN);

    const float* X = XA;
    float* Xn = XB;
    for (int l = 0; l < 2; l++) {
        aggregate_kernel<<<(N_NEWS * 32 + 255) / 256, 256>>>(X, off0, s0, inv0, A0, N_NEWS);
        aggregate_kernel<<<(N_INT  * 32 + 255) / 256, 256>>>(X, off1, s1, inv1, A1, N_INT);
        aggregate_kernel<<<(N_NEWS * 32 + 255) / 256, 256>>>(X, off2, s2, inv2, A2, N_NEWS);

        // O = X @ W_root[l] + conv_b[l]
        mma_gemm_kernel<false><<<dim3(2, (N_ALL + 127) / 128), 256>>>(
            X, Bhi + WOFF_ROOT + l * 65536, Blo + WOFF_ROOT + l * 65536,
            nullptr, conv_b + (size_t)l * H, O, N_ALL, H);
        // O[:news] += A0 @ W_rel[l,0]
        mma_gemm_kernel<false><<<dim3(2, (N_NEWS + 127) / 128), 256>>>(
            A0, Bhi + WOFF_REL + (l * 3 + 0) * 65536, Blo + WOFF_REL + (l * 3 + 0) * 65536,
            O, nullptr, O, N_NEWS, H);
        // Xn[int] = relu(O[int] + A1 @ W_rel[l,1])
        mma_gemm_kernel<true><<<dim3(2, (N_INT + 127) / 128), 256>>>(
            A1, Bhi + WOFF_REL + (l * 3 + 1) * 65536, Blo + WOFF_REL + (l * 3 + 1) * 65536,
            O + (size_t)N_NEWS * H, nullptr, Xn + (size_t)N_NEWS * H, N_INT, H);
        // Xn[news] = relu(O[news] + A2 @ W_rel[l,2])
        mma_gemm_kernel<true><<<dim3(2, (N_NEWS + 127) / 128), 256>>>(
            A2, Bhi + WOFF_REL + (l * 3 + 2) * 65536, Blo + WOFF_REL + (l * 3 + 2) * 65536,
            O, nullptr, Xn, N_NEWS, H);

        const float* tmp = X;
        X = Xn;
        Xn = (float*)tmp;
    }

    out_proj_kernel<<<(N_NEWS + 31) / 32, 256>>>(X, out_W, out_b, out);
}

// round 8
// speedup vs baseline: 1.8964x; 1.0535x over previous
#include <cuda_runtime.h>
#include <cuda_bf16.h>
#include <cstdint>
#include <cstddef>

// Problem constants
#define N_NEWS 10000
#define N_INT  50000
#define N_ALL  60000
#define F_IN   768
#define H      256
#define OUTD   8
#define NNODE  70000          // deg/inv/cur table: [0,10000) r0-news, [10000,60000) r1-int, [60000,70000) r2-news
#define ETOT   1300000

// ---------------- device scratch (no allocations allowed) ----------------
// Concatenated-K activation buffers (ping-pong across layers):
//   CN[10000][768]: cols 0-255 X_news, 256-511 A0, 512-767 A2
//   CI[50000][512]: cols 0-255 X_int,  256-511 A1
__device__ float g_CN0[N_NEWS * 768];
__device__ float g_CN1[N_NEWS * 768];
__device__ float g_CI0[N_INT * 512];
__device__ float g_CI1[N_INT * 512];

__device__ int   g_deg[NNODE];
__device__ float g_inv[NNODE];
__device__ int   g_off[NNODE + 3];   // off0@0 (10001), off1@10001 (50001), off2@60002 (10001)
__device__ int   g_cur[NNODE];
__device__ int   g_srt[ETOT];

// Split/transposed weights, [256 N][K] bf16, hi & lo. Concatenated layout:
//  ENC_N @0 (K=768), ENC_I @196608 (K=768),
//  L0N @393216 (K=768: Wroot0|Wrel00|Wrel02), L0I @589824 (K=512: Wroot0|Wrel01),
//  L1N @720896, L1I @917504.  Total 1048576.
#define WOFF_ENCN 0
#define WOFF_ENCI 196608
#define WOFF_LN(l) (393216 + (l) * 327680)
#define WOFF_LI(l) (589824 + (l) * 327680)
#define WTOTAL 1048576
__device__ __nv_bfloat16 g_Bhi[WTOTAL];
__device__ __nv_bfloat16 g_Blo[WTOTAL];

// ================= helpers =================
__device__ __forceinline__ uint32_t smem_u32(const void* p) {
    uint32_t a;
    asm("{ .reg .u64 t; cvta.to.shared.u64 t, %1; cvt.u32.u64 %0, t; }" : "=r"(a) : "l"(p));
    return a;
}
__device__ __forceinline__ uint32_t pack_bf2(__nv_bfloat16 a, __nv_bfloat16 b) {
    return (uint32_t)__bfloat16_as_ushort(a) | ((uint32_t)__bfloat16_as_ushort(b) << 16);
}
__device__ __forceinline__ void ldm_x4(uint32_t& r0, uint32_t& r1, uint32_t& r2, uint32_t& r3,
                                       uint32_t addr) {
    asm volatile("ldmatrix.sync.aligned.m8n8.x4.shared.b16 {%0,%1,%2,%3}, [%4];"
                 : "=r"(r0), "=r"(r1), "=r"(r2), "=r"(r3) : "r"(addr));
}
__device__ __forceinline__ void mma_bf16(float* c, uint32_t a0, uint32_t a1, uint32_t a2,
                                         uint32_t a3, uint32_t b0, uint32_t b1) {
    asm volatile("mma.sync.aligned.m16n8k16.row.col.f32.bf16.bf16.f32 "
                 "{%0,%1,%2,%3}, {%4,%5,%6,%7}, {%8,%9}, {%0,%1,%2,%3};"
                 : "+f"(c[0]), "+f"(c[1]), "+f"(c[2]), "+f"(c[3])
                 : "r"(a0), "r"(a1), "r"(a2), "r"(a3), "r"(b0), "r"(b1));
}
__device__ __forceinline__ void cp16(uint32_t dst, const void* src) {
    asm volatile("cp.async.cg.shared.global [%0], [%1], 16;" :: "r"(dst), "l"(src));
}

// ================= pipelined HMMA GEMM (3-term bf16 split) =================
// C[M, 0:256 of ldc] = A[M][K](fp32) @ B[K,256]; B pre-transposed/split [256][K] bf16.
// Block 128x128 (grid.x=2 covers N=256), BK=32, 8 warps (4m x 2n), warp tile 32x64.
// Double-buffered dyn SMEM: per buf {Ah,Al,Bh,Bl} each 128x40 bf16 (10240 B) -> 40960/buf.
#define BKP 40
#define BUFSZ 40960
#define GSMEM (2 * BUFSZ)

__device__ __forceinline__ void gemm_ldA(const float* __restrict__ A, int K, int M,
                                         int row0, int fRow, int fHalf, int k0, float4* aR) {
    const int r = row0 + fRow;
    if (r < M) {
        const float* ap = A + (size_t)r * K + k0 + fHalf * 16;
        aR[0] = __ldg((const float4*)ap);
        aR[1] = __ldg((const float4*)(ap + 4));
        aR[2] = __ldg((const float4*)(ap + 8));
        aR[3] = __ldg((const float4*)(ap + 12));
    } else {
        aR[0] = aR[1] = aR[2] = aR[3] = make_float4(0.f, 0.f, 0.f, 0.f);
    }
}
__device__ __forceinline__ void gemm_stA(char* bufbase, int fRow, int fHalf, const float4* aR) {
    uint32_t* dh = (uint32_t*)(bufbase + fRow * 80 + fHalf * 32);
    uint32_t* dl = (uint32_t*)(bufbase + 10240 + fRow * 80 + fHalf * 32);
    #pragma unroll
    for (int j = 0; j < 4; j++) {
        float4 v = aR[j];
        __nv_bfloat16 hx = __float2bfloat16(v.x), hy = __float2bfloat16(v.y);
        __nv_bfloat16 hz = __float2bfloat16(v.z), hw = __float2bfloat16(v.w);
        dh[2 * j]     = pack_bf2(hx, hy);
        dh[2 * j + 1] = pack_bf2(hz, hw);
        dl[2 * j]     = pack_bf2(__float2bfloat16(v.x - __bfloat162float(hx)),
                                 __float2bfloat16(v.y - __bfloat162float(hy)));
        dl[2 * j + 1] = pack_bf2(__float2bfloat16(v.z - __bfloat162float(hz)),
                                 __float2bfloat16(v.w - __bfloat162float(hw)));
    }
}
__device__ __forceinline__ void gemm_ldB(uint32_t bufb, const __nv_bfloat16* __restrict__ Bth,
                                         const __nv_bfloat16* __restrict__ Btl,
                                         int K, int col0, int fRow, int fHalf, int k0) {
    const size_t gb = (size_t)(col0 + fRow) * K + k0 + fHalf * 16;
    const uint32_t d = bufb + 20480 + (uint32_t)(fRow * 80 + fHalf * 32);
    cp16(d, Bth + gb);
    cp16(d + 16, Bth + gb + 8);
    cp16(d + 10240, Btl + gb);
    cp16(d + 10240 + 16, Btl + gb + 8);
    asm volatile("cp.async.commit_group;" ::: "memory");
}

template <bool RELU>
__global__ __launch_bounds__(256) void mma_gemm_kernel(
    const float* __restrict__ A,
    const __nv_bfloat16* __restrict__ Bth,
    const __nv_bfloat16* __restrict__ Btl,
    const float* __restrict__ bias,
    float* __restrict__ Cout, int ldc,
    int M, int K) {
    extern __shared__ char smem[];
    const uint32_t sb = smem_u32(smem);
    const int tid  = threadIdx.x;
    const int wid  = tid >> 5;
    const int lane = tid & 31;
    const int wm   = wid & 3;
    const int wn   = wid >> 2;
    const int row0 = blockIdx.y * 128;
    const int col0 = blockIdx.x * 128;
    const int fRow = tid >> 1;
    const int fHalf = tid & 1;

    float acc[2][8][4];
    #pragma unroll
    for (int i = 0; i < 2; i++)
        #pragma unroll
        for (int j = 0; j < 8; j++)
            #pragma unroll
            for (int q = 0; q < 4; q++) acc[i][j][q] = 0.f;

    const int nchunks = K >> 5;
    float4 aR[4];

    // prologue: chunk 0 -> buf 0
    gemm_ldA(A, K, M, row0, fRow, fHalf, 0, aR);
    gemm_ldB(sb, Bth, Btl, K, col0, fRow, fHalf, 0);
    gemm_stA(smem, fRow, fHalf, aR);
    asm volatile("cp.async.wait_group 0;" ::: "memory");
    __syncthreads();

    for (int c = 0; c < nchunks; c++) {
        const int b = c & 1;
        const bool nxt = (c + 1) < nchunks;
        if (nxt) {
            const int k0 = (c + 1) << 5;
            gemm_ldA(A, K, M, row0, fRow, fHalf, k0, aR);
            gemm_ldB(sb + (b ^ 1) * BUFSZ, Bth, Btl, K, col0, fRow, fHalf, k0);
        }

        // compute on buffer b
        const uint32_t aHb = sb + b * BUFSZ;
        const uint32_t aLb = aHb + 10240;
        const uint32_t bHb = aHb + 20480;
        const uint32_t bLb = aHb + 30720;
        #pragma unroll
        for (int kk = 0; kk < 2; kk++) {
            uint32_t ah[2][4], al[2][4];
            #pragma unroll
            for (int mt = 0; mt < 2; mt++) {
                const uint32_t roff =
                    (uint32_t)(wm * 32 + mt * 16 + ((lane >> 3) & 1) * 8 + (lane & 7)) * 80
                    + kk * 32 + (lane >> 4) * 16;
                ldm_x4(ah[mt][0], ah[mt][1], ah[mt][2], ah[mt][3], aHb + roff);
                ldm_x4(al[mt][0], al[mt][1], al[mt][2], al[mt][3], aLb + roff);
            }
            #pragma unroll
            for (int ng = 0; ng < 4; ng++) {
                const uint32_t boff =
                    (uint32_t)(wn * 64 + ng * 16 + ((lane >> 4) & 1) * 8 + (lane & 7)) * 80
                    + kk * 32 + ((lane >> 3) & 1) * 16;
                uint32_t bh[4], bl[4];
                ldm_x4(bh[0], bh[1], bh[2], bh[3], bHb + boff);
                ldm_x4(bl[0], bl[1], bl[2], bl[3], bLb + boff);
                #pragma unroll
                for (int mt = 0; mt < 2; mt++) {
                    #pragma unroll
                    for (int h = 0; h < 2; h++) {
                        float* cc = acc[mt][ng * 2 + h];
                        mma_bf16(cc, ah[mt][0], ah[mt][1], ah[mt][2], ah[mt][3],
                                 bh[2 * h], bh[2 * h + 1]);
                        mma_bf16(cc, ah[mt][0], ah[mt][1], ah[mt][2], ah[mt][3],
                                 bl[2 * h], bl[2 * h + 1]);
                        mma_bf16(cc, al[mt][0], al[mt][1], al[mt][2], al[mt][3],
                                 bh[2 * h], bh[2 * h + 1]);
                    }
                }
            }
        }

        if (nxt) {
            gemm_stA(smem + (b ^ 1) * BUFSZ, fRow, fHalf, aR);
            asm volatile("cp.async.wait_group 0;" ::: "memory");
        }
        __syncthreads();
    }

    // ---- epilogue (bias + optional relu; output cols 0-255 of row stride ldc) ----
    const int colBase = col0 + wn * 64 + (lane & 3) * 2;
    #pragma unroll
    for (int mt = 0; mt < 2; mt++) {
        #pragma unroll
        for (int half = 0; half < 2; half++) {
            const int r = row0 + wm * 32 + mt * 16 + (lane >> 2) + half * 8;
            if (r < M) {
                #pragma unroll
                for (int nt = 0; nt < 8; nt++) {
                    const int c = colBase + nt * 8;
                    float v0 = acc[mt][nt][2 * half];
                    float v1 = acc[mt][nt][2 * half + 1];
                    const float2 bb = *(const float2*)(bias + c);
                    v0 += bb.x; v1 += bb.y;
                    if (RELU) { v0 = fmaxf(v0, 0.f); v1 = fmaxf(v1, 0.f); }
                    *(float2*)(Cout + (size_t)r * ldc + c) = make_float2(v0, v1);
                }
            }
        }
    }
}

// ---------------- single-launch weight prep (transpose + bf16 split + concat) ----
__global__ void wprep_all_kernel(const float* __restrict__ Wn, const float* __restrict__ Wi,
                                 const float* __restrict__ W_rel, const float* __restrict__ W_root,
                                 __nv_bfloat16* __restrict__ Bhi, __nv_bfloat16* __restrict__ Blo) {
    int idx = blockIdx.x * blockDim.x + threadIdx.x;
    if (idx >= WTOTAL) return;
    const float* src;
    int base, Kdst, koff, s;
    if (idx < 196608) {
        base = WOFF_ENCN; Kdst = 768; koff = 0; s = idx; src = Wn;
    } else if (idx < 393216) {
        base = WOFF_ENCI; Kdst = 768; koff = 0; s = idx - 196608; src = Wi;
    } else {
        int t = idx - 393216;
        const int l = (t >= 327680) ? 1 : 0;
        if (l) t -= 327680;
        if (t < 196608) {  // news concat: Wroot | Wrel0 | Wrel2
            base = WOFF_LN(l); Kdst = 768;
            const int j = t >> 16;
            s = t & 65535;
            koff = j * 256;
            src = (j == 0) ? (W_root + l * 65536)
                           : (W_rel + (l * 3 + ((j == 1) ? 0 : 2)) * 65536);
        } else {           // int concat: Wroot | Wrel1
            t -= 196608;
            base = WOFF_LI(l); Kdst = 512;
            const int j = t >> 16;
            s = t & 65535;
            koff = j * 256;
            src = (j == 0) ? (W_root + l * 65536) : (W_rel + (l * 3 + 1) * 65536);
        }
    }
    const int k = s >> 8;
    const int n = s & 255;
    const float v = src[k * 256 + n];
    const __nv_bfloat16 h = __float2bfloat16(v);
    const size_t d = (size_t)base + (size_t)n * Kdst + koff + k;
    Bhi[d] = h;
    Blo[d] = __float2bfloat16(v - __bfloat162float(h));
}

// ---------------- CSR build: merged kernels over unified node table ----------------
__global__ void deg_all_kernel(const int* __restrict__ d0, const int* __restrict__ d1,
                               const int* __restrict__ d2, int E0, int E01, int ET,
                               int* __restrict__ deg) {
    int e = blockIdx.x * blockDim.x + threadIdx.x;
    if (e >= ET) return;
    if (e < E0)       atomicAdd(&deg[d0[e]], 1);
    else if (e < E01) atomicAdd(&deg[10000 + d1[e - E0]], 1);
    else              atomicAdd(&deg[60000 + d2[e - E01]], 1);
}

__global__ void invdeg_kernel(const int* __restrict__ deg, float* __restrict__ inv) {
    int i = blockIdx.x * blockDim.x + threadIdx.x;
    if (i < NNODE) {
        int d = deg[i];
        inv[i] = (d > 0) ? (1.0f / (float)d) : 0.0f;
    }
}

// 3 blocks, one per relation segment; exclusive scan with global srt base added.
__global__ __launch_bounds__(1024) void scan3_kernel(const int* __restrict__ deg,
                                                     int* __restrict__ off,
                                                     int* __restrict__ cur,
                                                     int E0, int E1) {
    __shared__ int warpsum[32];
    int dbase, n, obase, sbase;
    if (blockIdx.x == 0)      { dbase = 0;     n = 10000; obase = 0;     sbase = 0; }
    else if (blockIdx.x == 1) { dbase = 10000; n = 50000; obase = 10001; sbase = E0; }
    else                      { dbase = 60000; n = 10000; obase = 60002; sbase = E0 + E1; }

    const int t = (int)threadIdx.x;
    const int CH = (n + 1023) >> 10;
    const int start = t * CH;

    int local = 0;
    for (int c = 0; c < CH; c++) {
        int i = start + c;
        if (i < n) local += deg[dbase + i];
    }
    int lane = t & 31, w = t >> 5;
    int v = local;
    #pragma unroll
    for (int s = 1; s < 32; s <<= 1) {
        int u = __shfl_up_sync(0xFFFFFFFFu, v, s);
        if (lane >= s) v += u;
    }
    if (lane == 31) warpsum[w] = v;
    __syncthreads();
    if (w == 0) {
        int ws = warpsum[lane];
        #pragma unroll
        for (int s = 1; s < 32; s <<= 1) {
            int u = __shfl_up_sync(0xFFFFFFFFu, ws, s);
            if (lane >= s) ws += u;
        }
        warpsum[lane] = ws;
    }
    __syncthreads();
    int run = sbase + (v - local) + (w > 0 ? warpsum[w - 1] : 0);
    for (int c = 0; c < CH; c++) {
        int i = start + c;
        if (i < n) {
            off[obase + i] = run;
            cur[dbase + i] = run;
            run += deg[dbase + i];
        }
    }
    if (t == 1023) off[obase + n] = run;
}

__global__ void fill_all_kernel(const int* __restrict__ s0, const int* __restrict__ d0,
                                const int* __restrict__ s1, const int* __restrict__ d1,
                                const int* __restrict__ s2, const int* __restrict__ d2,
                                int E0, int E01, int ET,
                                int* __restrict__ cur, int* __restrict__ srt) {
    int e = blockIdx.x * blockDim.x + threadIdx.x;
    if (e >= ET) return;
    int di, sv;
    if (e < E0)       { di = d0[e];                 sv = s0[e]; }
    else if (e < E01) { di = 10000 + d1[e - E0];    sv = s1[e - E0]; }
    else              { di = 60000 + d2[e - E01];   sv = s2[e - E01] + 10000; }
    int p = atomicAdd(&cur[di], 1);
    srt[p] = sv;
}

// ---------------- merged mean aggregation (all 3 relations, warp per node) --------
// Writes A0/A2 into CN cols 256-511 / 512-767, A1 into CI cols 256-511.
__global__ void agg_all_kernel(float* __restrict__ CN, float* __restrict__ CI,
                               const int* __restrict__ off, const int* __restrict__ srt,
                               const float* __restrict__ inv) {
    const int gw   = (int)((blockIdx.x * blockDim.x + threadIdx.x) >> 5);
    const int lane = threadIdx.x & 31;
    if (gw >= NNODE) return;
    const int* offp;
    float* outp;
    if (gw < 10000) {
        offp = off + gw;
        outp = CN + (size_t)gw * 768 + 256;
    } else if (gw < 60000) {
        const int i = gw - 10000;
        offp = off + 10001 + i;
        outp = CI + (size_t)i * 512 + 256;
    } else {
        const int i = gw - 60000;
        offp = off + 60002 + i;
        outp = CN + (size_t)i * 768 + 512;
    }
    const int e0 = offp[0], e1 = offp[1];
    float4 sA = make_float4(0.f, 0.f, 0.f, 0.f);
    float4 sB = make_float4(0.f, 0.f, 0.f, 0.f);
    for (int e = e0; e < e1; e++) {
        const int src = srt[e];
        const float* xr = (src < 10000) ? (CN + (size_t)src * 768)
                                        : (CI + (size_t)(src - 10000) * 512);
        const float4* row = (const float4*)xr;
        float4 v0 = __ldg(&row[lane]);
        float4 v1 = __ldg(&row[lane + 32]);
        sA.x += v0.x; sA.y += v0.y; sA.z += v0.z; sA.w += v0.w;
        sB.x += v1.x; sB.y += v1.y; sB.z += v1.z; sB.w += v1.w;
    }
    const float d = inv[gw];
    sA.x *= d; sA.y *= d; sA.z *= d; sA.w *= d;
    sB.x *= d; sB.y *= d; sB.z *= d; sB.w *= d;
    float4* o = (float4*)outp;
    o[lane]      = sA;
    o[lane + 32] = sB;
}

// ---------------- final projection: out = X[:10000] @ W(256x8) + b ----------------
__global__ void out_proj_kernel(const float* __restrict__ X,
                                const float* __restrict__ W,
                                const float* __restrict__ b,
                                float* __restrict__ out) {
    int i = blockIdx.x * 32 + (threadIdx.x >> 3);
    int o = threadIdx.x & 7;
    if (i >= N_NEWS) return;
    float s = b[o];
    const float* x = X + (size_t)i * 768;
    #pragma unroll 8
    for (int j = 0; j < H; j++) s += x[j] * __ldg(&W[j * OUTD + o]);
    out[i * OUTD + o] = s;
}

// ---------------- launch ----------------
extern "C" void kernel_launch(void* const* d_in, const int* in_sizes, int n_in,
                              void* d_out, int out_size) {
    const float* x_news = (const float*)d_in[0];
    const float* x_int  = (const float*)d_in[1];
    const float* Wn     = (const float*)d_in[2];
    const float* bn     = (const float*)d_in[3];
    const float* Wi     = (const float*)d_in[4];
    const float* bi     = (const float*)d_in[5];
    const float* W_rel  = (const float*)d_in[6];
    const float* W_root = (const float*)d_in[7];
    const float* conv_b = (const float*)d_in[8];
    const float* out_W  = (const float*)d_in[9];
    const float* out_b  = (const float*)d_in[10];
    const int* e0s = (const int*)d_in[11];
    const int* e0d = (const int*)d_in[12];
    const int* e1s = (const int*)d_in[13];
    const int* e1d = (const int*)d_in[14];
    const int* e2s = (const int*)d_in[15];
    const int* e2d = (const int*)d_in[16];
    const int E0 = in_sizes[11], E1 = in_sizes[13], E2 = in_sizes[15];
    const int E01 = E0 + E1, ET = E0 + E1 + E2;
    float* out = (float*)d_out;

    float *CN0, *CN1, *CI0, *CI1, *inv;
    int *deg, *off, *cur, *srt;
    __nv_bfloat16 *Bhi, *Blo;
    cudaGetSymbolAddress((void**)&CN0, g_CN0);
    cudaGetSymbolAddress((void**)&CN1, g_CN1);
    cudaGetSymbolAddress((void**)&CI0, g_CI0);
    cudaGetSymbolAddress((void**)&CI1, g_CI1);
    cudaGetSymbolAddress((void**)&deg, g_deg);
    cudaGetSymbolAddress((void**)&inv, g_inv);
    cudaGetSymbolAddress((void**)&off, g_off);
    cudaGetSymbolAddress((void**)&cur, g_cur);
    cudaGetSymbolAddress((void**)&srt, g_srt);
    cudaGetSymbolAddress((void**)&Bhi, g_Bhi);
    cudaGetSymbolAddress((void**)&Blo, g_Blo);

    cudaFuncSetAttribute(mma_gemm_kernel<false>,
                         cudaFuncAttributeMaxDynamicSharedMemorySize, GSMEM);
    cudaFuncSetAttribute(mma_gemm_kernel<true>,
                         cudaFuncAttributeMaxDynamicSharedMemorySize, GSMEM);

    // 1 launch: weight prep into concatenated split layout
    wprep_all_kernel<<<(WTOTAL + 255) / 256, 256>>>(Wn, Wi, W_rel, W_root, Bhi, Blo);

    // CSR build: 5 ops
    cudaMemsetAsync(deg, 0, NNODE * sizeof(int));
    deg_all_kernel<<<(ET + 255) / 256, 256>>>(e0d, e1d, e2d, E0, E01, ET, deg);
    invdeg_kernel<<<(NNODE + 255) / 256, 256>>>(deg, inv);
    scan3_kernel<<<3, 1024>>>(deg, off, cur, E0, E1);
    fill_all_kernel<<<(ET + 255) / 256, 256>>>(e0s, e0d, e1s, e1d, e2s, e2d,
                                               E0, E01, ET, cur, srt);

    // encode: X -> CN0 cols 0-255 (ldc 768), CI0 cols 0-255 (ldc 512)
    mma_gemm_kernel<false><<<dim3(2, (N_NEWS + 127) / 128), 256, GSMEM>>>(
        x_news, Bhi + WOFF_ENCN, Blo + WOFF_ENCN, bn, CN0, 768, N_NEWS, F_IN);
    mma_gemm_kernel<false><<<dim3(2, (N_INT + 127) / 128), 256, GSMEM>>>(
        x_int, Bhi + WOFF_ENCI, Blo + WOFF_ENCI, bi, CI0, 512, N_INT, F_IN);

    float* CNs[2] = {CN0, CN1};
    float* CIs[2] = {CI0, CI1};
    for (int l = 0; l < 2; l++) {
        float* CNc = CNs[l & 1];
        float* CIc = CIs[l & 1];
        float* CNn = CNs[(l + 1) & 1];
        float* CIn = CIs[(l + 1) & 1];

        // fill A0/A1/A2 into concat cols of the CURRENT buffers
        agg_all_kernel<<<(NNODE * 32 + 255) / 256, 256>>>(CNc, CIc, off, srt, inv);

        // fused per-type RGCN layer: relu(concat @ concatW + conv_b)
        mma_gemm_kernel<true><<<dim3(2, (N_NEWS + 127) / 128), 256, GSMEM>>>(
            CNc, Bhi + WOFF_LN(l), Blo + WOFF_LN(l), conv_b + (size_t)l * H,
            CNn, 768, N_NEWS, 768);
        mma_gemm_kernel<true><<<dim3(2, (N_INT + 127) / 128), 256, GSMEM>>>(
            CIc, Bhi + WOFF_LI(l), Blo + WOFF_LI(l), conv_b + (size_t)l * H,
            CIn, 512, N_INT, 512);
    }

    // final projection reads X = CN0 cols 0-255 (after 2 layers, ping-pong returns to 0)
    out_proj_kernel<<<(N_NEWS + 31) / 32, 256>>>(CN0, out_W, out_b, out);
}

// round 9
// speedup vs baseline: 2.0468x; 1.0793x over previous
#include <cuda_runtime.h>
#include <cuda_bf16.h>
#include <cstdint>
#include <cstddef>

// Problem constants
#define N_NEWS 10000
#define N_INT  50000
#define F_IN   768
#define H      256
#define OUTD   8
#define NNODE  70000          // [0,10000) r0-news, [10000,60000) r1-int, [60000,70000) r2-news
#define ETOT   1300000
#define NB_SCAN 69            // ceil(70000/1024)

// ---------------- device scratch ----------------
// Activations stored as SPLIT bf16 (hi/lo). Concatenated-K layout:
//   CN*[10000][768]: cols 0-255 X_news, 256-511 A0, 512-767 A2
//   CI*[50000][512]: cols 0-255 X_int,  256-511 A1
__device__ __nv_bfloat16 g_CN0h[N_NEWS * 768], g_CN0l[N_NEWS * 768];
__device__ __nv_bfloat16 g_CN1h[N_NEWS * 768], g_CN1l[N_NEWS * 768];
__device__ __nv_bfloat16 g_CI0h[N_INT * 512],  g_CI0l[N_INT * 512];
__device__ __nv_bfloat16 g_CI1h[N_INT * 512],  g_CI1l[N_INT * 512];

__device__ int   g_deg[NNODE];
__device__ float g_inv[NNODE];
__device__ int   g_off[NNODE + 1];
__device__ int   g_cur[NNODE];
__device__ int   g_srt[ETOT];
__device__ int   g_bsum[NB_SCAN];

// Split/transposed weights, [256 N][K] bf16, hi & lo. Concatenated layout:
#define WOFF_ENCN 0
#define WOFF_ENCI 196608
#define WOFF_LN(l) (393216 + (l) * 327680)
#define WOFF_LI(l) (589824 + (l) * 327680)
#define WTOTAL 1048576
__device__ __nv_bfloat16 g_Bhi[WTOTAL];
__device__ __nv_bfloat16 g_Blo[WTOTAL];

// ================= helpers =================
__device__ __forceinline__ uint32_t smem_u32(const void* p) {
    uint32_t a;
    asm("{ .reg .u64 t; cvta.to.shared.u64 t, %1; cvt.u32.u64 %0, t; }" : "=r"(a) : "l"(p));
    return a;
}
__device__ __forceinline__ uint32_t pack_bf2(__nv_bfloat16 a, __nv_bfloat16 b) {
    return (uint32_t)__bfloat16_as_ushort(a) | ((uint32_t)__bfloat16_as_ushort(b) << 16);
}
__device__ __forceinline__ void ldm_x4(uint32_t& r0, uint32_t& r1, uint32_t& r2, uint32_t& r3,
                                       uint32_t addr) {
    asm volatile("ldmatrix.sync.aligned.m8n8.x4.shared.b16 {%0,%1,%2,%3}, [%4];"
                 : "=r"(r0), "=r"(r1), "=r"(r2), "=r"(r3) : "r"(addr));
}
__device__ __forceinline__ void mma_bf16(float* c, uint32_t a0, uint32_t a1, uint32_t a2,
                                         uint32_t a3, uint32_t b0, uint32_t b1) {
    asm volatile("mma.sync.aligned.m16n8k16.row.col.f32.bf16.bf16.f32 "
                 "{%0,%1,%2,%3}, {%4,%5,%6,%7}, {%8,%9}, {%0,%1,%2,%3};"
                 : "+f"(c[0]), "+f"(c[1]), "+f"(c[2]), "+f"(c[3])
                 : "r"(a0), "r"(a1), "r"(a2), "r"(a3), "r"(b0), "r"(b1));
}
__device__ __forceinline__ void cp16(uint32_t dst, const void* src) {
    asm volatile("cp.async.cg.shared.global [%0], [%1], 16;" :: "r"(dst), "l"(src));
}
__device__ __forceinline__ void cp16z(uint32_t dst, const void* src, int sz) {
    asm volatile("cp.async.cg.shared.global [%0], [%1], 16, %2;" :: "r"(dst), "l"(src), "r"(sz));
}
// split a float into bf16 hi/lo
__device__ __forceinline__ void split_bf(float v, __nv_bfloat16& h, __nv_bfloat16& l) {
    h = __float2bfloat16(v);
    l = __float2bfloat16(v - __bfloat162float(h));
}

// ================= pipelined HMMA GEMM (3-term bf16 split) =================
// Block 128x128 (grid.x=2 covers N=256), BK=32, 8 warps (4m x 2n), warp tile 32x64.
// Dyn SMEM per buf: Ah@0, Al@10240, Bh@20480, Bl@30720 (128 rows x 80 B each).
#define BUFSZ 40960
#define GSMEM (2 * BUFSZ)

__device__ __forceinline__ void gemm_ldA_f32(const float* __restrict__ A, int K, int M,
                                             int row0, int fRow, int fHalf, int k0, float4* aR) {
    const int r = row0 + fRow;
    if (r < M) {
        const float* ap = A + (size_t)r * K + k0 + fHalf * 16;
        aR[0] = __ldg((const float4*)ap);
        aR[1] = __ldg((const float4*)(ap + 4));
        aR[2] = __ldg((const float4*)(ap + 8));
        aR[3] = __ldg((const float4*)(ap + 12));
    } else {
        aR[0] = aR[1] = aR[2] = aR[3] = make_float4(0.f, 0.f, 0.f, 0.f);
    }
}
__device__ __forceinline__ void gemm_stA(char* bufbase, int fRow, int fHalf, const float4* aR) {
    uint32_t* dh = (uint32_t*)(bufbase + fRow * 80 + fHalf * 32);
    uint32_t* dl = (uint32_t*)(bufbase + 10240 + fRow * 80 + fHalf * 32);
    #pragma unroll
    for (int j = 0; j < 4; j++) {
        float4 v = aR[j];
        __nv_bfloat16 hx, lx, hy, ly, hz, lz, hw, lw;
        split_bf(v.x, hx, lx); split_bf(v.y, hy, ly);
        split_bf(v.z, hz, lz); split_bf(v.w, hw, lw);
        dh[2 * j]     = pack_bf2(hx, hy);
        dh[2 * j + 1] = pack_bf2(hz, hw);
        dl[2 * j]     = pack_bf2(lx, ly);
        dl[2 * j + 1] = pack_bf2(lz, lw);
    }
}
__device__ __forceinline__ void gemm_ldA_split(uint32_t bufb,
                                               const __nv_bfloat16* __restrict__ Ahi,
                                               const __nv_bfloat16* __restrict__ Alo,
                                               int K, int M, int row0, int fRow, int fHalf, int k0) {
    const int r = row0 + fRow;
    const int sz = (r < M) ? 16 : 0;
    const int rc = (r < M) ? r : (M - 1);
    const size_t gb = (size_t)rc * K + k0 + fHalf * 16;
    const uint32_t d = bufb + (uint32_t)(fRow * 80 + fHalf * 32);
    cp16z(d,              Ahi + gb,     sz);
    cp16z(d + 16,         Ahi + gb + 8, sz);
    cp16z(d + 10240,      Alo + gb,     sz);
    cp16z(d + 10240 + 16, Alo + gb + 8, sz);
}
__device__ __forceinline__ void gemm_ldB(uint32_t bufb, const __nv_bfloat16* __restrict__ Bth,
                                         const __nv_bfloat16* __restrict__ Btl,
                                         int K, int col0, int fRow, int fHalf, int k0) {
    const size_t gb = (size_t)(col0 + fRow) * K + k0 + fHalf * 16;
    const uint32_t d = bufb + 20480 + (uint32_t)(fRow * 80 + fHalf * 32);
    cp16(d,              Bth + gb);
    cp16(d + 16,         Bth + gb + 8);
    cp16(d + 10240,      Btl + gb);
    cp16(d + 10240 + 16, Btl + gb + 8);
}

template <bool RELU, bool SPLITA>
__global__ __launch_bounds__(256) void mma_gemm_kernel(
    const float* __restrict__ A,              // used if !SPLITA
    const __nv_bfloat16* __restrict__ Ahi,    // used if SPLITA
    const __nv_bfloat16* __restrict__ Alo,
    const __nv_bfloat16* __restrict__ Bth,
    const __nv_bfloat16* __restrict__ Btl,
    const float* __restrict__ bias,
    __nv_bfloat16* __restrict__ Ch,
    __nv_bfloat16* __restrict__ Cl,
    int ldc, int M, int K) {
    extern __shared__ char smem[];
    const uint32_t sb = smem_u32(smem);
    const int tid  = threadIdx.x;
    const int wid  = tid >> 5;
    const int lane = tid & 31;
    const int wm   = wid & 3;
    const int wn   = wid >> 2;
    const int row0 = blockIdx.y * 128;
    const int col0 = blockIdx.x * 128;
    const int fRow = tid >> 1;
    const int fHalf = tid & 1;

    float acc[2][8][4];
    #pragma unroll
    for (int i = 0; i < 2; i++)
        #pragma unroll
        for (int j = 0; j < 8; j++)
            #pragma unroll
            for (int q = 0; q < 4; q++) acc[i][j][q] = 0.f;

    const int nchunks = K >> 5;
    float4 aR[4];

    // prologue: chunk 0 -> buf 0
    if (SPLITA) gemm_ldA_split(sb, Ahi, Alo, K, M, row0, fRow, fHalf, 0);
    else        gemm_ldA_f32(A, K, M, row0, fRow, fHalf, 0, aR);
    gemm_ldB(sb, Bth, Btl, K, col0, fRow, fHalf, 0);
    asm volatile("cp.async.commit_group;" ::: "memory");
    if (!SPLITA) gemm_stA(smem, fRow, fHalf, aR);
    asm volatile("cp.async.wait_group 0;" ::: "memory");
    __syncthreads();

    for (int c = 0; c < nchunks; c++) {
        const int b = c & 1;
        const bool nxt = (c + 1) < nchunks;
        if (nxt) {
            const int k0 = (c + 1) << 5;
            if (SPLITA) gemm_ldA_split(sb + (b ^ 1) * BUFSZ, Ahi, Alo, K, M, row0, fRow, fHalf, k0);
            else        gemm_ldA_f32(A, K, M, row0, fRow, fHalf, k0, aR);
            gemm_ldB(sb + (b ^ 1) * BUFSZ, Bth, Btl, K, col0, fRow, fHalf, k0);
            asm volatile("cp.async.commit_group;" ::: "memory");
        }

        const uint32_t aHb = sb + b * BUFSZ;
        const uint32_t aLb = aHb + 10240;
        const uint32_t bHb = aHb + 20480;
        const uint32_t bLb = aHb + 30720;
        #pragma unroll
        for (int kk = 0; kk < 2; kk++) {
            uint32_t ah[2][4], al[2][4];
            #pragma unroll
            for (int mt = 0; mt < 2; mt++) {
                const uint32_t roff =
                    (uint32_t)(wm * 32 + mt * 16 + ((lane >> 3) & 1) * 8 + (lane & 7)) * 80
                    + kk * 32 + (lane >> 4) * 16;
                ldm_x4(ah[mt][0], ah[mt][1], ah[mt][2], ah[mt][3], aHb + roff);
                ldm_x4(al[mt][0], al[mt][1], al[mt][2], al[mt][3], aLb + roff);
            }
            #pragma unroll
            for (int ng = 0; ng < 4; ng++) {
                const uint32_t boff =
                    (uint32_t)(wn * 64 + ng * 16 + ((lane >> 4) & 1) * 8 + (lane & 7)) * 80
                    + kk * 32 + ((lane >> 3) & 1) * 16;
                uint32_t bh[4], bl[4];
                ldm_x4(bh[0], bh[1], bh[2], bh[3], bHb + boff);
                ldm_x4(bl[0], bl[1], bl[2], bl[3], bLb + boff);
                #pragma unroll
                for (int mt = 0; mt < 2; mt++) {
                    #pragma unroll
                    for (int h = 0; h < 2; h++) {
                        float* cc = acc[mt][ng * 2 + h];
                        mma_bf16(cc, ah[mt][0], ah[mt][1], ah[mt][2], ah[mt][3],
                                 bh[2 * h], bh[2 * h + 1]);
                        mma_bf16(cc, ah[mt][0], ah[mt][1], ah[mt][2], ah[mt][3],
                                 bl[2 * h], bl[2 * h + 1]);
                        mma_bf16(cc, al[mt][0], al[mt][1], al[mt][2], al[mt][3],
                                 bh[2 * h], bh[2 * h + 1]);
                    }
                }
            }
        }

        if (nxt) {
            if (!SPLITA) gemm_stA(smem + (b ^ 1) * BUFSZ, fRow, fHalf, aR);
            asm volatile("cp.async.wait_group 0;" ::: "memory");
        }
        __syncthreads();
    }

    // ---- epilogue: bias + optional relu, split to bf16 hi/lo ----
    const int colBase = col0 + wn * 64 + (lane & 3) * 2;
    #pragma unroll
    for (int mt = 0; mt < 2; mt++) {
        #pragma unroll
        for (int half = 0; half < 2; half++) {
            const int r = row0 + wm * 32 + mt * 16 + (lane >> 2) + half * 8;
            if (r < M) {
                #pragma unroll
                for (int nt = 0; nt < 8; nt++) {
                    const int c = colBase + nt * 8;
                    float v0 = acc[mt][nt][2 * half];
                    float v1 = acc[mt][nt][2 * half + 1];
                    const float2 bb = *(const float2*)(bias + c);
                    v0 += bb.x; v1 += bb.y;
                    if (RELU) { v0 = fmaxf(v0, 0.f); v1 = fmaxf(v1, 0.f); }
                    __nv_bfloat16 h0, l0, h1, l1;
                    split_bf(v0, h0, l0);
                    split_bf(v1, h1, l1);
                    *(uint32_t*)(Ch + (size_t)r * ldc + c) = pack_bf2(h0, h1);
                    *(uint32_t*)(Cl + (size_t)r * ldc + c) = pack_bf2(l0, l1);
                }
            }
        }
    }
}

// ---------------- single-launch weight prep ----------------
__global__ void wprep_all_kernel(const float* __restrict__ Wn, const float* __restrict__ Wi,
                                 const float* __restrict__ W_rel, const float* __restrict__ W_root,
                                 __nv_bfloat16* __restrict__ Bhi, __nv_bfloat16* __restrict__ Blo) {
    int idx = blockIdx.x * blockDim.x + threadIdx.x;
    if (idx >= WTOTAL) return;
    const float* src;
    int base, Kdst, koff, s;
    if (idx < 196608) {
        base = WOFF_ENCN; Kdst = 768; koff = 0; s = idx; src = Wn;
    } else if (idx < 393216) {
        base = WOFF_ENCI; Kdst = 768; koff = 0; s = idx - 196608; src = Wi;
    } else {
        int t = idx - 393216;
        const int l = (t >= 327680) ? 1 : 0;
        if (l) t -= 327680;
        if (t < 196608) {
            base = WOFF_LN(l); Kdst = 768;
            const int j = t >> 16;
            s = t & 65535;
            koff = j * 256;
            src = (j == 0) ? (W_root + l * 65536)
                           : (W_rel + (l * 3 + ((j == 1) ? 0 : 2)) * 65536);
        } else {
            t -= 196608;
            base = WOFF_LI(l); Kdst = 512;
            const int j = t >> 16;
            s = t & 65535;
            koff = j * 256;
            src = (j == 0) ? (W_root + l * 65536) : (W_rel + (l * 3 + 1) * 65536);
        }
    }
    const int k = s >> 8;
    const int n = s & 255;
    const float v = src[k * 256 + n];
    __nv_bfloat16 h, l2;
    split_bf(v, h, l2);
    const size_t d = (size_t)base + (size_t)n * Kdst + koff + k;
    Bhi[d] = h;
    Blo[d] = l2;
}

// ---------------- CSR build ----------------
__global__ void deg_all_kernel(const int* __restrict__ d0, const int* __restrict__ d1,
                               const int* __restrict__ d2, int E0, int E01, int ET,
                               int* __restrict__ deg) {
    int e = blockIdx.x * blockDim.x + threadIdx.x;
    if (e >= ET) return;
    if (e < E0)       atomicAdd(&deg[d0[e]], 1);
    else if (e < E01) atomicAdd(&deg[10000 + d1[e - E0]], 1);
    else              atomicAdd(&deg[60000 + d2[e - E01]], 1);
}

// flat exclusive scan over 70000 degrees: phase 1 (per-block) + inv-degree
__global__ __launch_bounds__(256) void scan_p1(const int* __restrict__ deg,
                                               int* __restrict__ off,
                                               float* __restrict__ inv,
                                               int* __restrict__ bsum) {
    __shared__ int ws[8];
    const int t = (int)threadIdx.x;
    const int base = (blockIdx.x * 256 + t) * 4;
    int4 d = make_int4(0, 0, 0, 0);
    if (base < NNODE) {
        d = *(const int4*)(deg + base);
        *(float4*)(inv + base) = make_float4(
            d.x > 0 ? 1.f / (float)d.x : 0.f, d.y > 0 ? 1.f / (float)d.y : 0.f,
            d.z > 0 ? 1.f / (float)d.z : 0.f, d.w > 0 ? 1.f / (float)d.w : 0.f);
    }
    const int local = d.x + d.y + d.z + d.w;
    const int lane = t & 31, w = t >> 5;
    int v = local;
    #pragma unroll
    for (int s = 1; s < 32; s <<= 1) {
        int u = __shfl_up_sync(0xFFFFFFFFu, v, s);
        if (lane >= s) v += u;
    }
    if (lane == 31) ws[w] = v;
    __syncthreads();
    if (t == 0) {
        int run = 0;
        #pragma unroll
        for (int i = 0; i < 8; i++) { int x = ws[i]; ws[i] = run; run += x; }
        bsum[blockIdx.x] = run;
    }
    __syncthreads();
    const int excl = (v - local) + ws[w];
    if (base < NNODE) {
        off[base]     = excl;
        off[base + 1] = excl + d.x;
        off[base + 2] = excl + d.x + d.y;
        off[base + 3] = excl + d.x + d.y + d.z;
    }
}

// phase 2: scan NB_SCAN block sums (exclusive), write off[NNODE]=ET
__global__ __launch_bounds__(128) void scan_p2(int* __restrict__ bsum,
                                               int* __restrict__ off, int ET) {
    __shared__ int sh[128];
    const int t = (int)threadIdx.x;
    const int v = (t < NB_SCAN) ? bsum[t] : 0;
    sh[t] = v;
    __syncthreads();
    #pragma unroll
    for (int s = 1; s < 128; s <<= 1) {
        int u = (t >= s) ? sh[t - s] : 0;
        __syncthreads();
        sh[t] += u;
        __syncthreads();
    }
    if (t < NB_SCAN) bsum[t] = sh[t] - v;
    if (t == 0) off[NNODE] = ET;
}

// phase 3: add block prefix, write cur
__global__ __launch_bounds__(256) void scan_p3(int* __restrict__ off, int* __restrict__ cur,
                                               const int* __restrict__ bsum) {
    const int base = (blockIdx.x * 256 + (int)threadIdx.x) * 4;
    if (base < NNODE) {
        const int bs = bsum[blockIdx.x];
        int4 o = *(int4*)(off + base);
        o.x += bs; o.y += bs; o.z += bs; o.w += bs;
        *(int4*)(off + base) = o;
        *(int4*)(cur + base) = o;
    }
}

__global__ void fill_all_kernel(const int* __restrict__ s0, const int* __restrict__ d0,
                                const int* __restrict__ s1, const int* __restrict__ d1,
                                const int* __restrict__ s2, const int* __restrict__ d2,
                                int E0, int E01, int ET,
                                int* __restrict__ cur, int* __restrict__ srt) {
    int e = blockIdx.x * blockDim.x + threadIdx.x;
    if (e >= ET) return;
    int di, sv;
    if (e < E0)       { di = d0[e];               sv = s0[e]; }
    else if (e < E01) { di = 10000 + d1[e - E0];  sv = s1[e - E0]; }
    else              { di = 60000 + d2[e - E01]; sv = s2[e - E01] + 10000; }
    int p = atomicAdd(&cur[di], 1);
    srt[p] = sv;
}

// ---------------- merged mean aggregation (split bf16 in/out) ----------------
__device__ __forceinline__ void acc8(float* a, uint4 v) {
    const __nv_bfloat162* p = (const __nv_bfloat162*)&v;
    #pragma unroll
    for (int i = 0; i < 4; i++) {
        float2 f = __bfloat1622float2(p[i]);
        a[2 * i] += f.x;
        a[2 * i + 1] += f.y;
    }
}

__global__ void agg_all_kernel(__nv_bfloat16* __restrict__ CNh, __nv_bfloat16* __restrict__ CNl,
                               __nv_bfloat16* __restrict__ CIh, __nv_bfloat16* __restrict__ CIl,
                               const int* __restrict__ off, const int* __restrict__ srt,
                               const float* __restrict__ inv) {
    const int gw   = (int)((blockIdx.x * blockDim.x + threadIdx.x) >> 5);
    const int lane = threadIdx.x & 31;
    if (gw >= NNODE) return;
    __nv_bfloat16 *oh, *ol;
    if (gw < 10000) {
        oh = CNh + (size_t)gw * 768 + 256; ol = CNl + (size_t)gw * 768 + 256;
    } else if (gw < 60000) {
        const int i = gw - 10000;
        oh = CIh + (size_t)i * 512 + 256; ol = CIl + (size_t)i * 512 + 256;
    } else {
        const int i = gw - 60000;
        oh = CNh + (size_t)i * 768 + 512; ol = CNl + (size_t)i * 768 + 512;
    }
    const int e0 = off[gw], e1 = off[gw + 1];
    const int co = lane * 8;
    float a[8];
    #pragma unroll
    for (int i = 0; i < 8; i++) a[i] = 0.f;
    for (int e = e0; e < e1; e++) {
        const int src = srt[e];
        const __nv_bfloat16 *rh, *rl;
        if (src < 10000) { rh = CNh + (size_t)src * 768; rl = CNl + (size_t)src * 768; }
        else             { rh = CIh + (size_t)(src - 10000) * 512; rl = CIl + (size_t)(src - 10000) * 512; }
        uint4 hv = __ldg((const uint4*)(rh + co));
        uint4 lv = __ldg((const uint4*)(rl + co));
        acc8(a, hv);
        acc8(a, lv);
    }
    const float d = inv[gw];
    uint4 ho, lo_;
    uint32_t* hp = (uint32_t*)&ho;
    uint32_t* lp = (uint32_t*)&lo_;
    #pragma unroll
    for (int i = 0; i < 4; i++) {
        float v0 = a[2 * i] * d, v1 = a[2 * i + 1] * d;
        __nv_bfloat16 h0, l0, h1, l1;
        split_bf(v0, h0, l0);
        split_bf(v1, h1, l1);
        hp[i] = pack_bf2(h0, h1);
        lp[i] = pack_bf2(l0, l1);
    }
    *(uint4*)(oh + co) = ho;
    *(uint4*)(ol + co) = lo_;
}

// ---------------- final projection ----------------
__global__ void out_proj_kernel(const __nv_bfloat16* __restrict__ Xh,
                                const __nv_bfloat16* __restrict__ Xl,
                                const float* __restrict__ W,
                                const float* __restrict__ b,
                                float* __restrict__ out) {
    int i = blockIdx.x * 32 + (threadIdx.x >> 3);
    int o = threadIdx.x & 7;
    if (i >= N_NEWS) return;
    float s = b[o];
    const __nv_bfloat16* xh = Xh + (size_t)i * 768;
    const __nv_bfloat16* xl = Xl + (size_t)i * 768;
    #pragma unroll 8
    for (int j = 0; j < H; j++) {
        float x = __bfloat162float(xh[j]) + __bfloat162float(xl[j]);
        s += x * __ldg(&W[j * OUTD + o]);
    }
    out[i * OUTD + o] = s;
}

// ---------------- launch ----------------
extern "C" void kernel_launch(void* const* d_in, const int* in_sizes, int n_in,
                              void* d_out, int out_size) {
    const float* x_news = (const float*)d_in[0];
    const float* x_int  = (const float*)d_in[1];
    const float* Wn     = (const float*)d_in[2];
    const float* bn     = (const float*)d_in[3];
    const float* Wi     = (const float*)d_in[4];
    const float* bi     = (const float*)d_in[5];
    const float* W_rel  = (const float*)d_in[6];
    const float* W_root = (const float*)d_in[7];
    const float* conv_b = (const float*)d_in[8];
    const float* out_W  = (const float*)d_in[9];
    const float* out_b  = (const float*)d_in[10];
    const int* e0s = (const int*)d_in[11];
    const int* e0d = (const int*)d_in[12];
    const int* e1s = (const int*)d_in[13];
    const int* e1d = (const int*)d_in[14];
    const int* e2s = (const int*)d_in[15];
    const int* e2d = (const int*)d_in[16];
    const int E0 = in_sizes[11], E1 = in_sizes[13], E2 = in_sizes[15];
    const int E01 = E0 + E1, ET = E0 + E1 + E2;
    float* out = (float*)d_out;

    __nv_bfloat16 *CN0h, *CN0l, *CN1h, *CN1l, *CI0h, *CI0l, *CI1h, *CI1l, *Bhi, *Blo;
    float *inv;
    int *deg, *off, *cur, *srt, *bsum;
    cudaGetSymbolAddress((void**)&CN0h, g_CN0h);
    cudaGetSymbolAddress((void**)&CN0l, g_CN0l);
    cudaGetSymbolAddress((void**)&CN1h, g_CN1h);
    cudaGetSymbolAddress((void**)&CN1l, g_CN1l);
    cudaGetSymbolAddress((void**)&CI0h, g_CI0h);
    cudaGetSymbolAddress((void**)&CI0l, g_CI0l);
    cudaGetSymbolAddress((void**)&CI1h, g_CI1h);
    cudaGetSymbolAddress((void**)&CI1l, g_CI1l);
    cudaGetSymbolAddress((void**)&deg, g_deg);
    cudaGetSymbolAddress((void**)&inv, g_inv);
    cudaGetSymbolAddress((void**)&off, g_off);
    cudaGetSymbolAddress((void**)&cur, g_cur);
    cudaGetSymbolAddress((void**)&srt, g_srt);
    cudaGetSymbolAddress((void**)&bsum, g_bsum);
    cudaGetSymbolAddress((void**)&Bhi, g_Bhi);
    cudaGetSymbolAddress((void**)&Blo, g_Blo);

    cudaFuncSetAttribute((const void*)mma_gemm_kernel<false, false>,
                         cudaFuncAttributeMaxDynamicSharedMemorySize, GSMEM);
    cudaFuncSetAttribute((const void*)mma_gemm_kernel<true, true>,
                         cudaFuncAttributeMaxDynamicSharedMemorySize, GSMEM);

    // weight prep
    wprep_all_kernel<<<(WTOTAL + 255) / 256, 256>>>(Wn, Wi, W_rel, W_root, Bhi, Blo);

    // CSR build
    cudaMemsetAsync(deg, 0, NNODE * sizeof(int));
    deg_all_kernel<<<(ET + 255) / 256, 256>>>(e0d, e1d, e2d, E0, E01, ET, deg);
    scan_p1<<<NB_SCAN, 256>>>(deg, off, inv, bsum);
    scan_p2<<<1, 128>>>(bsum, off, ET);
    scan_p3<<<NB_SCAN, 256>>>(off, cur, bsum);
    fill_all_kernel<<<(ET + 255) / 256, 256>>>(e0s, e0d, e1s, e1d, e2s, e2d,
                                               E0, E01, ET, cur, srt);

    // encode (fp32 A path)
    mma_gemm_kernel<false, false><<<dim3(2, (N_NEWS + 127) / 128), 256, GSMEM>>>(
        x_news, nullptr, nullptr, Bhi + WOFF_ENCN, Blo + WOFF_ENCN, bn,
        CN0h, CN0l, 768, N_NEWS, F_IN);
    mma_gemm_kernel<false, false><<<dim3(2, (N_INT + 127) / 128), 256, GSMEM>>>(
        x_int, nullptr, nullptr, Bhi + WOFF_ENCI, Blo + WOFF_ENCI, bi,
        CI0h, CI0l, 512, N_INT, F_IN);

    __nv_bfloat16* CNhs[2] = {CN0h, CN1h};
    __nv_bfloat16* CNls[2] = {CN0l, CN1l};
    __nv_bfloat16* CIhs[2] = {CI0h, CI1h};
    __nv_bfloat16* CIls[2] = {CI0l, CI1l};
    for (int l = 0; l < 2; l++) {
        __nv_bfloat16 *CNch = CNhs[l & 1], *CNcl = CNls[l & 1];
        __nv_bfloat16 *CIch = CIhs[l & 1], *CIcl = CIls[l & 1];
        __nv_bfloat16 *CNnh = CNhs[(l + 1) & 1], *CNnl = CNls[(l + 1) & 1];
        __nv_bfloat16 *CInh = CIhs[(l + 1) & 1], *CInl = CIls[(l + 1) & 1];

        agg_all_kernel<<<(NNODE * 32 + 255) / 256, 256>>>(CNch, CNcl, CIch, CIcl, off, srt, inv);

        mma_gemm_kernel<true, true><<<dim3(2, (N_NEWS + 127) / 128), 256, GSMEM>>>(
            nullptr, CNch, CNcl, Bhi + WOFF_LN(l), Blo + WOFF_LN(l), conv_b + (size_t)l * H,
            CNnh, CNnl, 768, N_NEWS, 768);
        mma_gemm_kernel<true, true><<<dim3(2, (N_INT + 127) / 128), 256, GSMEM>>>(
            nullptr, CIch, CIcl, Bhi + WOFF_LI(l), Blo + WOFF_LI(l), conv_b + (size_t)l * H,
            CInh, CInl, 512, N_INT, 512);
    }

    out_proj_kernel<<<(N_NEWS + 31) / 32, 256>>>(CN0h, CN0l, out_W, out_b, out);
}